// round 1
// baseline (speedup 1.0000x reference)
#include <cuda_runtime.h>
#include <cuda_bf16.h>
#include <math.h>

#define NN    50000
#define EDG   800000
#define K1    3
#define INC   128
#define NF    64
#define CCH   128   // 2*NF
#define LABEL 10

// ---------------- scratch (device globals; no allocs allowed) ----------------
__device__ float g_Ar[K1][NN * NF];   // X @ W[k] (real source), per k
__device__ float g_Ai[K1][NN * NF];   // X @ W[k] (imag source), per k
__device__ float g_Hr[NN * NF];       // current hidden (real, post-activation)
__device__ float g_Hi[NN * NF];
__device__ float g_accR[NN * NF];     // SpMM accumulators
__device__ float g_accI[NN * NF];
__device__ float g_cmean[CCH];
__device__ float g_ca[CCH];
__device__ float g_smean[NN];
__device__ float g_smax[NN];

// ---------------- vector reduction (fire-and-forget atomic add) -------------
__device__ __forceinline__ void red4(float* p, float4 v) {
    asm volatile("red.global.add.v4.f32 [%0], {%1,%2,%3,%4};"
                 :: "l"(p), "f"(v.x), "f"(v.y), "f"(v.z), "f"(v.w) : "memory");
}

// ---------------- GEMM: Out[k,ri] = H(ri) @ W[k], H:[NN,FIN], W:[FIN,NF] ----
// grid.x tiles 128 rows; grid.y = 6 (k*2 + ri). block = 256 (tx:8 colgroups, ty:32).
template<int FIN, bool FROMG>
__global__ void gemm_k(const float* __restrict__ HrIn, const float* __restrict__ HiIn,
                       const float* __restrict__ Wall) {
    const int z  = blockIdx.y;
    const int k  = z >> 1, ri = z & 1;
    const float* H;
    if (FROMG) H = ri ? g_Hi : g_Hr;
    else       H = ri ? HiIn : HrIn;
    const float* W = Wall + k * FIN * NF;
    float* Out = ri ? g_Ai[k] : g_Ar[k];

    const int row0 = blockIdx.x * 128;
    const int tid  = threadIdx.x;
    const int tx   = tid & 7;       // col group: cols tx*8 .. tx*8+7
    const int ty   = tid >> 3;      // 0..31 ; rows ty + j*32

    __shared__ float Hs[128][33];   // +1 pad: conflict-free row reads
    __shared__ float Ws[32][64];

    float4 accA[4], accB[4];
    #pragma unroll
    for (int j = 0; j < 4; j++) { accA[j] = make_float4(0,0,0,0); accB[j] = make_float4(0,0,0,0); }

    for (int kc = 0; kc < FIN; kc += 32) {
        // load H tile [128 x 32]
        for (int idx = tid; idx < 128 * 32; idx += 256) {
            int r = idx >> 5, i = idx & 31;
            int gr = row0 + r;
            Hs[r][i] = (gr < NN) ? H[gr * FIN + kc + i] : 0.f;
        }
        // load W tile [32 x 64]
        for (int idx = tid; idx < 32 * 64; idx += 256) {
            int i = idx >> 6, c = idx & 63;
            Ws[i][c] = W[(kc + i) * NF + c];
        }
        __syncthreads();
        #pragma unroll 8
        for (int i = 0; i < 32; i++) {
            float4 wa = *(const float4*)&Ws[i][tx * 8];
            float4 wb = *(const float4*)&Ws[i][tx * 8 + 4];
            #pragma unroll
            for (int j = 0; j < 4; j++) {
                float h = Hs[ty + j * 32][i];
                accA[j].x += h * wa.x; accA[j].y += h * wa.y;
                accA[j].z += h * wa.z; accA[j].w += h * wa.w;
                accB[j].x += h * wb.x; accB[j].y += h * wb.y;
                accB[j].z += h * wb.z; accB[j].w += h * wb.w;
            }
        }
        __syncthreads();
    }
    #pragma unroll
    for (int j = 0; j < 4; j++) {
        int gr = row0 + ty + j * 32;
        if (gr < NN) {
            *(float4*)&Out[gr * NF + tx * 8]     = accA[j];
            *(float4*)&Out[gr * NF + tx * 8 + 4] = accB[j];
        }
    }
}

// ---------------- init accumulators with bias -------------------------------
__global__ void init_acc_k(const float* __restrict__ b) {
    int idx = blockIdx.x * 256 + threadIdx.x;
    if (idx < NN * NF) {
        float v = b[idx & (NF - 1)];
        g_accR[idx] = v;
        g_accI[idx] = v;
    }
}

// ---------------- SpMM scatter: 4 threads per edge, vector atomics ----------
__global__ void spmm_k(const int* __restrict__ rows, const int* __restrict__ cols,
                       const float* __restrict__ vr, const float* __restrict__ vi) {
    int gid = blockIdx.x * 256 + threadIdx.x;   // < K1*EDG*4 = 9.6M
    int q = gid & 3;
    int e = gid >> 2;                            // flat over [K1*EDG)
    if (e >= K1 * EDG) return;
    int k = e / EDG;
    int r = rows[e];
    int c = cols[e];
    float a = vr[e];
    float b = vi[e];
    const float* Ar = &g_Ar[k][c * NF];
    const float* Ai = &g_Ai[k][c * NF];
    float* dR = &g_accR[r * NF];
    float* dI = &g_accI[r * NF];
    #pragma unroll
    for (int j = 0; j < 4; j++) {
        int off = j * 16 + q * 4;                // lanes of an edge contiguous per inst
        float4 x = *(const float4*)&Ar[off];
        float4 y = *(const float4*)&Ai[off];
        float4 re = make_float4(a*x.x - b*y.x, a*x.y - b*y.y, a*x.z - b*y.z, a*x.w - b*y.w);
        float4 im = make_float4(b*x.x + a*y.x, b*x.y + a*y.y, b*x.z + a*y.z, b*x.w + a*y.w);
        red4(dR + off, re);
        red4(dI + off, im);
    }
}

// ---------------- complex ReLU (gated on real part) --------------------------
__global__ void act_k() {
    int idx = blockIdx.x * 256 + threadIdx.x;
    if (idx < NN * NF) {
        float re = g_accR[idx];
        float im = g_accI[idx];
        bool m = (re >= 0.f);
        g_Hr[idx] = m ? re : 0.f;
        g_Hi[idx] = m ? im : 0.f;
    }
}

// ---------------- CBAM channel attention -------------------------------------
__global__ void zero_cmean_k() {
    if (threadIdx.x < CCH) g_cmean[threadIdx.x] = 0.f;
}

__global__ void chan_sum_k() {
    const int NPB = 512;
    int t = threadIdx.x;            // 256
    int c = t & 127;
    int half = t >> 7;
    int n0 = blockIdx.x * NPB;
    int n1 = min(n0 + NPB, NN);
    const float* src = (c < NF) ? g_Hr : g_Hi;
    int cc = c & (NF - 1);
    float s = 0.f;
    for (int n = n0 + half; n < n1; n += 2) s += src[n * NF + cc];
    __shared__ float sm[256];
    sm[t] = s;
    __syncthreads();
    if (t < 128) atomicAdd(&g_cmean[c], sm[t] + sm[t + 128]);
}

__global__ void ca_k(const float* __restrict__ w1, const float* __restrict__ w2) {
    __shared__ float avg[CCH];
    __shared__ float hid[8];
    int t = threadIdx.x;            // 128
    avg[t] = g_cmean[t] * (1.f / (float)NN);
    __syncthreads();
    if (t < 8) {
        float s = 0.f;
        #pragma unroll 4
        for (int c = 0; c < CCH; c++) s += w1[t * CCH + c] * avg[c];
        hid[t] = fmaxf(s, 0.f);
    }
    __syncthreads();
    float o = 0.f;
    #pragma unroll
    for (int r = 0; r < 8; r++) o += w2[t * 8 + r] * hid[r];
    g_ca[t] = 1.f / (1.f + expf(-o));
}

// ---------------- spatial stats (after CA scaling) ---------------------------
__global__ void sstat_k() {
    __shared__ float ca[CCH];
    if (threadIdx.x < CCH) ca[threadIdx.x] = g_ca[threadIdx.x];
    __syncthreads();
    int n = blockIdx.x * blockDim.x + threadIdx.x;
    if (n >= NN) return;
    float sum = 0.f, mx = -1e30f;
    const float4* hr = (const float4*)&g_Hr[n * NF];
    #pragma unroll
    for (int j = 0; j < 16; j++) {
        float4 v = hr[j];
        float a0 = v.x * ca[j*4+0], a1 = v.y * ca[j*4+1];
        float a2 = v.z * ca[j*4+2], a3 = v.w * ca[j*4+3];
        sum += a0 + a1 + a2 + a3;
        mx = fmaxf(mx, fmaxf(fmaxf(a0, a1), fmaxf(a2, a3)));
    }
    const float4* hi = (const float4*)&g_Hi[n * NF];
    #pragma unroll
    for (int j = 0; j < 16; j++) {
        float4 v = hi[j];
        float a0 = v.x * ca[64+j*4+0], a1 = v.y * ca[64+j*4+1];
        float a2 = v.z * ca[64+j*4+2], a3 = v.w * ca[64+j*4+3];
        sum += a0 + a1 + a2 + a3;
        mx = fmaxf(mx, fmaxf(fmaxf(a0, a1), fmaxf(a2, a3)));
    }
    g_smean[n] = sum * (1.f / (float)CCH);
    g_smax[n]  = mx;
}

// ---------------- spatial attention + final conv + log_softmax ---------------
__global__ void final_k(const float* __restrict__ sa_w,
                        const float* __restrict__ conv_w,
                        const float* __restrict__ conv_b,
                        float* __restrict__ out) {
    __shared__ float ca[CCH];
    __shared__ float cw[LABEL * CCH];
    __shared__ float cb[LABEL];
    __shared__ float sw[14];
    int t = threadIdx.x;
    if (t < CCH) ca[t] = g_ca[t];
    for (int idx = t; idx < LABEL * CCH; idx += blockDim.x) cw[idx] = conv_w[idx];
    if (t < LABEL) cb[t] = conv_b[t];
    if (t < 14) sw[t] = sa_w[t];
    __syncthreads();

    int n = blockIdx.x * blockDim.x + t;
    if (n >= NN) return;

    // 7-tap spatial conv over [mean;max], zero-padded
    float s = 0.f;
    #pragma unroll
    for (int tap = 0; tap < 7; tap++) {
        int m = n - 3 + tap;
        if (m >= 0 && m < NN) s += sw[tap] * g_smean[m] + sw[7 + tap] * g_smax[m];
    }
    float sa = 1.f / (1.f + expf(-s));

    float acc[LABEL];
    #pragma unroll
    for (int l = 0; l < LABEL; l++) acc[l] = cb[l];

    const float* hr = &g_Hr[n * NF];
    const float* hi = &g_Hi[n * NF];
    #pragma unroll 4
    for (int c = 0; c < NF; c++) {
        float xv = hr[c] * ca[c] * sa;
        #pragma unroll
        for (int l = 0; l < LABEL; l++) acc[l] += cw[l * CCH + c] * xv;
    }
    #pragma unroll 4
    for (int c = 0; c < NF; c++) {
        float xv = hi[c] * ca[NF + c] * sa;
        #pragma unroll
        for (int l = 0; l < LABEL; l++) acc[l] += cw[l * CCH + NF + c] * xv;
    }

    float mx = acc[0];
    #pragma unroll
    for (int l = 1; l < LABEL; l++) mx = fmaxf(mx, acc[l]);
    float se = 0.f;
    #pragma unroll
    for (int l = 0; l < LABEL; l++) se += expf(acc[l] - mx);
    float lse = logf(se) + mx;
    #pragma unroll
    for (int l = 0; l < LABEL; l++) out[l * NN + n] = acc[l] - lse;
}

// ---------------- launch sequence --------------------------------------------
extern "C" void kernel_launch(void* const* d_in, const int* in_sizes, int n_in,
                              void* d_out, int out_size) {
    const float* Xr    = (const float*)d_in[0];
    const float* Xi    = (const float*)d_in[1];
    const int*   rows  = (const int*)  d_in[2];
    const int*   cols  = (const int*)  d_in[3];
    const float* vr    = (const float*)d_in[4];
    const float* vi    = (const float*)d_in[5];
    const float* w0    = (const float*)d_in[6];
    const float* b0    = (const float*)d_in[7];
    const float* w1    = (const float*)d_in[8];
    const float* b1    = (const float*)d_in[9];
    const float* w2    = (const float*)d_in[10];
    const float* b2    = (const float*)d_in[11];
    const float* caw1  = (const float*)d_in[12];
    const float* caw2  = (const float*)d_in[13];
    const float* saw   = (const float*)d_in[14];
    const float* convw = (const float*)d_in[15];
    const float* convb = (const float*)d_in[16];
    float* out = (float*)d_out;

    const dim3 gemm_grid((NN + 127) / 128, 6);
    const int elem_blocks = (NN * NF + 255) / 256;
    const int spmm_blocks = (K1 * EDG * 4 + 255) / 256;
    const int node_blocks = (NN + 255) / 256;

    // ---- layer 0 (FIN=128, inputs from d_in) ----
    gemm_k<INC, false><<<gemm_grid, 256>>>(Xr, Xi, w0);
    init_acc_k<<<elem_blocks, 256>>>(b0);
    spmm_k<<<spmm_blocks, 256>>>(rows, cols, vr, vi);
    act_k<<<elem_blocks, 256>>>();

    // ---- layer 1 (FIN=64, inputs from g_H) ----
    gemm_k<NF, true><<<gemm_grid, 256>>>(nullptr, nullptr, w1);
    init_acc_k<<<elem_blocks, 256>>>(b1);
    spmm_k<<<spmm_blocks, 256>>>(rows, cols, vr, vi);
    act_k<<<elem_blocks, 256>>>();

    // ---- layer 2 ----
    gemm_k<NF, true><<<gemm_grid, 256>>>(nullptr, nullptr, w2);
    init_acc_k<<<elem_blocks, 256>>>(b2);
    spmm_k<<<spmm_blocks, 256>>>(rows, cols, vr, vi);
    act_k<<<elem_blocks, 256>>>();

    // ---- CBAM + head ----
    zero_cmean_k<<<1, 128>>>();
    chan_sum_k<<<(NN + 511) / 512, 256>>>();
    ca_k<<<1, 128>>>(caw1, caw2);
    sstat_k<<<node_blocks, 256>>>();
    final_k<<<node_blocks, 256>>>(saw, convw, convb, out);
}

// round 3
// speedup vs baseline: 1.2294x; 1.2294x over previous
#include <cuda_runtime.h>
#include <cuda_bf16.h>
#include <math.h>

#define NN    50000
#define EDG   800000
#define K1    3
#define INC   128
#define NF    64
#define CCH   128   // 2*NF
#define LABEL 10
#define TOTE  (K1*EDG)

// ---------------- scratch (device globals; no allocs allowed) ----------------
__device__ float g_A[(size_t)K1 * NN * CCH]; // per (k,node): [0..63]=real feat, [64..127]=imag
__device__ float g_Hr[NN * NF];              // current hidden (real, post-activation)
__device__ float g_Hi[NN * NF];
__device__ int   g_cnt[NN + 1];
__device__ int   g_off[NN + 1];
__device__ int   g_cursor[NN];
__device__ int4  g_epay[TOTE];               // (k*NN+c, bits(vr), bits(vi), 0)
__device__ float g_cmean[CCH];
__device__ float g_ca[CCH];
__device__ float g_smean[NN];
__device__ float g_smax[NN];

// ---------------- GEMM: A[k,:,ri*64..] = H(ri) @ W[k], H:[NN,FIN], W:[FIN,NF]
// grid.x tiles 128 rows; grid.y = 6 (k*2 + ri). block = 256.
template<int FIN, bool FROMG>
__global__ void gemm_k(const float* __restrict__ HrIn, const float* __restrict__ HiIn,
                       const float* __restrict__ Wall) {
    const int z  = blockIdx.y;
    const int k  = z >> 1, ri = z & 1;
    const float* H;
    if (FROMG) H = ri ? g_Hi : g_Hr;
    else       H = ri ? HiIn : HrIn;
    const float* W = Wall + k * FIN * NF;
    float* Out = g_A + (size_t)k * NN * CCH + ri * NF;   // row stride CCH

    const int row0 = blockIdx.x * 128;
    const int tid  = threadIdx.x;
    const int tx   = tid & 7;       // col group: cols tx*8 .. tx*8+7
    const int ty   = tid >> 3;      // 0..31 ; rows ty + j*32

    __shared__ float Hs[128][33];
    __shared__ float Ws[32][64];

    float4 accA[4], accB[4];
    #pragma unroll
    for (int j = 0; j < 4; j++) { accA[j] = make_float4(0,0,0,0); accB[j] = make_float4(0,0,0,0); }

    for (int kc = 0; kc < FIN; kc += 32) {
        for (int idx = tid; idx < 128 * 32; idx += 256) {
            int r = idx >> 5, i = idx & 31;
            int gr = row0 + r;
            Hs[r][i] = (gr < NN) ? H[gr * FIN + kc + i] : 0.f;
        }
        for (int idx = tid; idx < 32 * 64; idx += 256) {
            int i = idx >> 6, c = idx & 63;
            Ws[i][c] = W[(kc + i) * NF + c];
        }
        __syncthreads();
        #pragma unroll 8
        for (int i = 0; i < 32; i++) {
            float4 wa = *(const float4*)&Ws[i][tx * 8];
            float4 wb = *(const float4*)&Ws[i][tx * 8 + 4];
            #pragma unroll
            for (int j = 0; j < 4; j++) {
                float h = Hs[ty + j * 32][i];
                accA[j].x += h * wa.x; accA[j].y += h * wa.y;
                accA[j].z += h * wa.z; accA[j].w += h * wa.w;
                accB[j].x += h * wb.x; accB[j].y += h * wb.y;
                accB[j].z += h * wb.z; accB[j].w += h * wb.w;
            }
        }
        __syncthreads();
    }
    #pragma unroll
    for (int j = 0; j < 4; j++) {
        int gr = row0 + ty + j * 32;
        if (gr < NN) {
            *(float4*)&Out[gr * CCH + tx * 8]     = accA[j];
            *(float4*)&Out[gr * CCH + tx * 8 + 4] = accB[j];
        }
    }
}

// ---------------- CSR build (once per launch; topology shared by 3 layers) ---
__global__ void zero_cnt_k() {
    int i = blockIdx.x * 256 + threadIdx.x;
    if (i <= NN) g_cnt[i] = 0;
}

__global__ void hist_k(const int* __restrict__ rows) {
    int e = blockIdx.x * 256 + threadIdx.x;
    if (e < TOTE) atomicAdd(&g_cnt[rows[e]], 1);
}

// one-block exclusive scan: 1024 threads x 49-element chunks
__global__ void scan_k() {
    const int CHUNK = 49;                 // 1024*49 = 50176 >= NN+1
    __shared__ int sm[1024];
    int t = threadIdx.x;
    int base = t * CHUNK;
    int sum = 0;
    #pragma unroll
    for (int i = 0; i < CHUNK; i++) {
        int idx = base + i;
        if (idx < NN) sum += g_cnt[idx];
    }
    sm[t] = sum;
    __syncthreads();
    #pragma unroll
    for (int d = 1; d < 1024; d <<= 1) {
        int v = (t >= d) ? sm[t - d] : 0;
        __syncthreads();
        sm[t] += v;
        __syncthreads();
    }
    int run = (t == 0) ? 0 : sm[t - 1];
    #pragma unroll
    for (int i = 0; i < CHUNK; i++) {
        int idx = base + i;
        if (idx < NN) {
            g_off[idx]    = run;
            g_cursor[idx] = run;
            run += g_cnt[idx];
        } else if (idx == NN) {
            g_off[NN] = run;
        }
    }
}

__global__ void scatter_k(const int* __restrict__ rows, const int* __restrict__ cols,
                          const float* __restrict__ vr, const float* __restrict__ vi) {
    int e = blockIdx.x * 256 + threadIdx.x;
    if (e >= TOTE) return;
    int k = (e >= 2 * EDG) ? 2 : (e >= EDG) ? 1 : 0;   // no integer divide
    int r = rows[e];
    int pos = atomicAdd(&g_cursor[r], 1);
    g_epay[pos] = make_int4(k * NN + cols[e],
                            __float_as_int(vr[e]),
                            __float_as_int(vi[e]), 0);
}

// ---------------- SpMM gather: warp per row, fused bias + complex ReLU -------
__global__ void spmm_gather_k(const float* __restrict__ bias) {
    int w    = (blockIdx.x * 256 + threadIdx.x) >> 5;
    int lane = threadIdx.x & 31;
    if (w >= NN) return;

    float2 bv = *(const float2*)&bias[lane * 2];
    float2 aR = bv, aI = bv;

    int beg = g_off[w], end = g_off[w + 1];
    int e = beg;
    // 2-edge unroll for MLP
    for (; e + 1 < end; e += 2) {
        int4 p0 = g_epay[e];
        int4 p1 = g_epay[e + 1];
        const float2* A0 = (const float2*)&g_A[(size_t)p0.x * CCH];
        const float2* A1 = (const float2*)&g_A[(size_t)p1.x * CCH];
        float2 x0 = A0[lane],      y0 = A0[32 + lane];
        float2 x1 = A1[lane],      y1 = A1[32 + lane];
        float a0 = __int_as_float(p0.y), b0 = __int_as_float(p0.z);
        float a1 = __int_as_float(p1.y), b1 = __int_as_float(p1.z);
        aR.x = fmaf(a0, x0.x, fmaf(-b0, y0.x, aR.x));
        aR.y = fmaf(a0, x0.y, fmaf(-b0, y0.y, aR.y));
        aI.x = fmaf(b0, x0.x, fmaf( a0, y0.x, aI.x));
        aI.y = fmaf(b0, x0.y, fmaf( a0, y0.y, aI.y));
        aR.x = fmaf(a1, x1.x, fmaf(-b1, y1.x, aR.x));
        aR.y = fmaf(a1, x1.y, fmaf(-b1, y1.y, aR.y));
        aI.x = fmaf(b1, x1.x, fmaf( a1, y1.x, aI.x));
        aI.y = fmaf(b1, x1.y, fmaf( a1, y1.y, aI.y));
    }
    if (e < end) {
        int4 p = g_epay[e];
        const float2* A = (const float2*)&g_A[(size_t)p.x * CCH];
        float2 x = A[lane], y = A[32 + lane];
        float a = __int_as_float(p.y), b = __int_as_float(p.z);
        aR.x = fmaf(a, x.x, fmaf(-b, y.x, aR.x));
        aR.y = fmaf(a, x.y, fmaf(-b, y.y, aR.y));
        aI.x = fmaf(b, x.x, fmaf( a, y.x, aI.x));
        aI.y = fmaf(b, x.y, fmaf( a, y.y, aI.y));
    }

    // complex ReLU gated on real part
    float2 hr, hi;
    hr.x = (aR.x >= 0.f) ? aR.x : 0.f;  hi.x = (aR.x >= 0.f) ? aI.x : 0.f;
    hr.y = (aR.y >= 0.f) ? aR.y : 0.f;  hi.y = (aR.y >= 0.f) ? aI.y : 0.f;
    *(float2*)&g_Hr[w * NF + lane * 2] = hr;
    *(float2*)&g_Hi[w * NF + lane * 2] = hi;
}

// ---------------- CBAM channel attention -------------------------------------
__global__ void zero_cmean_k() {
    if (threadIdx.x < CCH) g_cmean[threadIdx.x] = 0.f;
}

__global__ void chan_sum_k() {
    const int NPB = 512;
    int t = threadIdx.x;            // 256
    int c = t & 127;
    int half = t >> 7;
    int n0 = blockIdx.x * NPB;
    int n1 = min(n0 + NPB, NN);
    const float* src = (c < NF) ? g_Hr : g_Hi;
    int cc = c & (NF - 1);
    float s = 0.f;
    for (int n = n0 + half; n < n1; n += 2) s += src[n * NF + cc];
    __shared__ float sm[256];
    sm[t] = s;
    __syncthreads();
    if (t < 128) atomicAdd(&g_cmean[c], sm[t] + sm[t + 128]);
}

__global__ void ca_k(const float* __restrict__ w1, const float* __restrict__ w2) {
    __shared__ float avg[CCH];
    __shared__ float hid[8];
    int t = threadIdx.x;            // 128
    avg[t] = g_cmean[t] * (1.f / (float)NN);
    __syncthreads();
    if (t < 8) {
        float s = 0.f;
        #pragma unroll 4
        for (int c = 0; c < CCH; c++) s += w1[t * CCH + c] * avg[c];
        hid[t] = fmaxf(s, 0.f);
    }
    __syncthreads();
    float o = 0.f;
    #pragma unroll
    for (int r = 0; r < 8; r++) o += w2[t * 8 + r] * hid[r];
    g_ca[t] = 1.f / (1.f + expf(-o));
}

// ---------------- spatial stats (after CA scaling) ---------------------------
__global__ void sstat_k() {
    __shared__ float ca[CCH];
    if (threadIdx.x < CCH) ca[threadIdx.x] = g_ca[threadIdx.x];
    __syncthreads();
    int n = blockIdx.x * blockDim.x + threadIdx.x;
    if (n >= NN) return;
    float sum = 0.f, mx = -1e30f;
    const float4* hr = (const float4*)&g_Hr[n * NF];
    #pragma unroll
    for (int j = 0; j < 16; j++) {
        float4 v = hr[j];
        float a0 = v.x * ca[j*4+0], a1 = v.y * ca[j*4+1];
        float a2 = v.z * ca[j*4+2], a3 = v.w * ca[j*4+3];
        sum += a0 + a1 + a2 + a3;
        mx = fmaxf(mx, fmaxf(fmaxf(a0, a1), fmaxf(a2, a3)));
    }
    const float4* hi = (const float4*)&g_Hi[n * NF];
    #pragma unroll
    for (int j = 0; j < 16; j++) {
        float4 v = hi[j];
        float a0 = v.x * ca[64+j*4+0], a1 = v.y * ca[64+j*4+1];
        float a2 = v.z * ca[64+j*4+2], a3 = v.w * ca[64+j*4+3];
        sum += a0 + a1 + a2 + a3;
        mx = fmaxf(mx, fmaxf(fmaxf(a0, a1), fmaxf(a2, a3)));
    }
    g_smean[n] = sum * (1.f / (float)CCH);
    g_smax[n]  = mx;
}

// ---------------- spatial attention + final conv + log_softmax ---------------
__global__ void final_k(const float* __restrict__ sa_w,
                        const float* __restrict__ conv_w,
                        const float* __restrict__ conv_b,
                        float* __restrict__ out) {
    __shared__ float ca[CCH];
    __shared__ float cw[LABEL * CCH];
    __shared__ float cb[LABEL];
    __shared__ float sw[14];
    int t = threadIdx.x;
    if (t < CCH) ca[t] = g_ca[t];
    for (int idx = t; idx < LABEL * CCH; idx += blockDim.x) cw[idx] = conv_w[idx];
    if (t < LABEL) cb[t] = conv_b[t];
    if (t < 14) sw[t] = sa_w[t];
    __syncthreads();

    int n = blockIdx.x * blockDim.x + t;
    if (n >= NN) return;

    float s = 0.f;
    #pragma unroll
    for (int tap = 0; tap < 7; tap++) {
        int m = n - 3 + tap;
        if (m >= 0 && m < NN) s += sw[tap] * g_smean[m] + sw[7 + tap] * g_smax[m];
    }
    float sa = 1.f / (1.f + expf(-s));

    float acc[LABEL];
    #pragma unroll
    for (int l = 0; l < LABEL; l++) acc[l] = cb[l];

    const float* hr = &g_Hr[n * NF];
    const float* hi = &g_Hi[n * NF];
    #pragma unroll 4
    for (int c = 0; c < NF; c++) {
        float xv = hr[c] * ca[c] * sa;
        #pragma unroll
        for (int l = 0; l < LABEL; l++) acc[l] += cw[l * CCH + c] * xv;
    }
    #pragma unroll 4
    for (int c = 0; c < NF; c++) {
        float xv = hi[c] * ca[NF + c] * sa;
        #pragma unroll
        for (int l = 0; l < LABEL; l++) acc[l] += cw[l * CCH + NF + c] * xv;
    }

    float mx = acc[0];
    #pragma unroll
    for (int l = 1; l < LABEL; l++) mx = fmaxf(mx, acc[l]);
    float se = 0.f;
    #pragma unroll
    for (int l = 0; l < LABEL; l++) se += expf(acc[l] - mx);
    float lse = logf(se) + mx;
    #pragma unroll
    for (int l = 0; l < LABEL; l++) out[l * NN + n] = acc[l] - lse;
}

// ---------------- launch sequence --------------------------------------------
extern "C" void kernel_launch(void* const* d_in, const int* in_sizes, int n_in,
                              void* d_out, int out_size) {
    const float* Xr    = (const float*)d_in[0];
    const float* Xi    = (const float*)d_in[1];
    const int*   rows  = (const int*)  d_in[2];
    const int*   cols  = (const int*)  d_in[3];
    const float* vr    = (const float*)d_in[4];
    const float* vi    = (const float*)d_in[5];
    const float* w0    = (const float*)d_in[6];
    const float* b0    = (const float*)d_in[7];
    const float* w1    = (const float*)d_in[8];
    const float* b1    = (const float*)d_in[9];
    const float* w2    = (const float*)d_in[10];
    const float* b2    = (const float*)d_in[11];
    const float* caw1  = (const float*)d_in[12];
    const float* caw2  = (const float*)d_in[13];
    const float* saw   = (const float*)d_in[14];
    const float* convw = (const float*)d_in[15];
    const float* convb = (const float*)d_in[16];
    float* out = (float*)d_out;

    const dim3 gemm_grid((NN + 127) / 128, 6);
    const int edge_blocks   = (TOTE + 255) / 256;
    const int gather_blocks = (NN * 32 + 255) / 256;
    const int node_blocks   = (NN + 255) / 256;

    // ---- CSR build (reused by all 3 layers) ----
    zero_cnt_k<<<(NN + 256) / 256, 256>>>();
    hist_k<<<edge_blocks, 256>>>(rows);
    scan_k<<<1, 1024>>>();
    scatter_k<<<edge_blocks, 256>>>(rows, cols, vr, vi);

    // ---- layer 0 (FIN=128, inputs from d_in) ----
    gemm_k<INC, false><<<gemm_grid, 256>>>(Xr, Xi, w0);
    spmm_gather_k<<<gather_blocks, 256>>>(b0);

    // ---- layer 1 ----
    gemm_k<NF, true><<<gemm_grid, 256>>>(nullptr, nullptr, w1);
    spmm_gather_k<<<gather_blocks, 256>>>(b1);

    // ---- layer 2 ----
    gemm_k<NF, true><<<gemm_grid, 256>>>(nullptr, nullptr, w2);
    spmm_gather_k<<<gather_blocks, 256>>>(b2);

    // ---- CBAM + head ----
    zero_cmean_k<<<1, 128>>>();
    chan_sum_k<<<(NN + 511) / 512, 256>>>();
    ca_k<<<1, 128>>>(caw1, caw2);
    sstat_k<<<node_blocks, 256>>>();
    final_k<<<node_blocks, 256>>>(saw, convw, convb, out);
}

// round 4
// speedup vs baseline: 1.5612x; 1.2699x over previous
#include <cuda_runtime.h>
#include <cuda_bf16.h>
#include <cuda_fp16.h>
#include <math.h>

#define NN    50000
#define EDG   800000
#define K1    3
#define INC   128
#define NF    64
#define CCH   128   // 2*NF
#define LABEL 10
#define TOTE  (K1*EDG)

// packed fp32x2 FMA (Blackwell-only SASS FFMA2; ptxas never emits it from C++)
#define FMA2(d, a, b) \
    asm("fma.rn.f32x2 %0, %1, %2, %0;" : "+l"(d) : "l"(a), "l"(b))
#define PACKF2(d, lo, hi) \
    asm("mov.b64 %0, {%1, %2};" : "=l"(d) : "f"(lo), "f"(hi))
#define UNPACKF2(lo, hi, s) \
    asm("mov.b64 {%0, %1}, %2;" : "=f"(lo), "=f"(hi) : "l"(s))
#define PACKH2(d, lo, hi) \
    asm("cvt.rn.f16x2.f32 %0, %1, %2;" : "=r"(d) : "f"(hi), "f"(lo))

// ---------------- scratch (device globals; no allocs allowed) ----------------
__device__ __half g_A[(size_t)K1 * NN * CCH]; // per (k,node): [0..63]=real, [64..127]=imag (fp16)
__device__ float g_Hr[NN * NF];               // current hidden (real, post-activation)
__device__ float g_Hi[NN * NF];
__device__ int   g_cnt[NN + 1];
__device__ int   g_off[NN + 1];
__device__ int   g_cursor[NN];
__device__ int4  g_epay[TOTE];                // (k*NN+c, bits(vr), bits(vi), 0)
__device__ float g_cmean[CCH];
__device__ float g_ca[CCH];
__device__ float g_smean[NN];
__device__ float g_smax[NN];

// ---------------- GEMM: A[k,:,ri*64..] = H(ri) @ W[k] -> fp16 out ------------
// grid.x tiles 128 rows; grid.y = 6 (k*2 + ri). block = 256.
// inner loop uses packed f32x2 FMA: col-paired u64 accumulators.
template<int FIN, bool FROMG>
__global__ void gemm_k(const float* __restrict__ HrIn, const float* __restrict__ HiIn,
                       const float* __restrict__ Wall) {
    const int z  = blockIdx.y;
    const int k  = z >> 1, ri = z & 1;
    const float* H;
    if (FROMG) H = ri ? g_Hi : g_Hr;
    else       H = ri ? HiIn : HrIn;
    const float* W = Wall + k * FIN * NF;
    __half* Out = g_A + (size_t)k * NN * CCH + ri * NF;   // row stride CCH halfs

    const int row0 = blockIdx.x * 128;
    const int tid  = threadIdx.x;
    const int tx   = tid & 7;       // col group: cols tx*8 .. tx*8+7
    const int ty   = tid >> 3;      // 0..31 ; rows ty + j*32

    __shared__ float Hs[128][33];
    __shared__ float Ws[32][64];

    unsigned long long acc[4][4];   // [row j][col pair] ; pair = (c, c+1)
    #pragma unroll
    for (int j = 0; j < 4; j++)
        #pragma unroll
        for (int p = 0; p < 4; p++) acc[j][p] = 0ull;

    for (int kc = 0; kc < FIN; kc += 32) {
        for (int idx = tid; idx < 128 * 32; idx += 256) {
            int r = idx >> 5, i = idx & 31;
            int gr = row0 + r;
            Hs[r][i] = (gr < NN) ? H[gr * FIN + kc + i] : 0.f;
        }
        for (int idx = tid; idx < 32 * 64; idx += 256) {
            int i = idx >> 6, c = idx & 63;
            Ws[i][c] = W[(kc + i) * NF + c];
        }
        __syncthreads();
        #pragma unroll 8
        for (int i = 0; i < 32; i++) {
            // 4 col-pairs of W as two 16B shared loads (adjacent reg pairs)
            longlong2 w01 = *(const longlong2*)&Ws[i][tx * 8];       // pairs (c0,c1),(c2,c3)
            longlong2 w23 = *(const longlong2*)&Ws[i][tx * 8 + 4];   // pairs (c4,c5),(c6,c7)
            #pragma unroll
            for (int j = 0; j < 4; j++) {
                float h = Hs[ty + j * 32][i];
                unsigned long long hh;
                PACKF2(hh, h, h);
                FMA2(acc[j][0], hh, (unsigned long long)w01.x);
                FMA2(acc[j][1], hh, (unsigned long long)w01.y);
                FMA2(acc[j][2], hh, (unsigned long long)w23.x);
                FMA2(acc[j][3], hh, (unsigned long long)w23.y);
            }
        }
        __syncthreads();
    }
    #pragma unroll
    for (int j = 0; j < 4; j++) {
        int gr = row0 + ty + j * 32;
        if (gr < NN) {
            uint4 st;
            float lo, hi;
            UNPACKF2(lo, hi, acc[j][0]); PACKH2(st.x, lo, hi);
            UNPACKF2(lo, hi, acc[j][1]); PACKH2(st.y, lo, hi);
            UNPACKF2(lo, hi, acc[j][2]); PACKH2(st.z, lo, hi);
            UNPACKF2(lo, hi, acc[j][3]); PACKH2(st.w, lo, hi);
            *(uint4*)&Out[(size_t)gr * CCH + tx * 8] = st;
        }
    }
}

// ---------------- CSR build (once per launch; topology shared by 3 layers) ---
__global__ void zero_cnt_k() {
    int i = blockIdx.x * 256 + threadIdx.x;
    if (i <= NN) g_cnt[i] = 0;
}

__global__ void hist_k(const int* __restrict__ rows) {
    int e = blockIdx.x * 256 + threadIdx.x;
    if (e < TOTE) atomicAdd(&g_cnt[rows[e]], 1);
}

// one-block exclusive scan: 1024 threads x 49-element chunks
__global__ void scan_k() {
    const int CHUNK = 49;                 // 1024*49 = 50176 >= NN+1
    __shared__ int sm[1024];
    int t = threadIdx.x;
    int base = t * CHUNK;
    int sum = 0;
    #pragma unroll
    for (int i = 0; i < CHUNK; i++) {
        int idx = base + i;
        if (idx < NN) sum += g_cnt[idx];
    }
    sm[t] = sum;
    __syncthreads();
    #pragma unroll
    for (int d = 1; d < 1024; d <<= 1) {
        int v = (t >= d) ? sm[t - d] : 0;
        __syncthreads();
        sm[t] += v;
        __syncthreads();
    }
    int run = (t == 0) ? 0 : sm[t - 1];
    #pragma unroll
    for (int i = 0; i < CHUNK; i++) {
        int idx = base + i;
        if (idx < NN) {
            g_off[idx]    = run;
            g_cursor[idx] = run;
            run += g_cnt[idx];
        } else if (idx == NN) {
            g_off[NN] = run;
        }
    }
}

__global__ void scatter_k(const int* __restrict__ rows, const int* __restrict__ cols,
                          const float* __restrict__ vr, const float* __restrict__ vi) {
    int e = blockIdx.x * 256 + threadIdx.x;
    if (e >= TOTE) return;
    int k = (e >= 2 * EDG) ? 2 : (e >= EDG) ? 1 : 0;   // no integer divide
    int r = rows[e];
    int pos = atomicAdd(&g_cursor[r], 1);
    g_epay[pos] = make_int4(k * NN + cols[e],
                            __float_as_int(vr[e]),
                            __float_as_int(vi[e]), 0);
}

// ---------------- SpMM gather: warp per row, fused bias + complex ReLU -------
__global__ void spmm_gather_k(const float* __restrict__ bias) {
    int w    = (blockIdx.x * 256 + threadIdx.x) >> 5;
    int lane = threadIdx.x & 31;
    if (w >= NN) return;

    float2 bv = *(const float2*)&bias[lane * 2];
    float2 aR = bv, aI = bv;

    int beg = g_off[w], end = g_off[w + 1];
    int e = beg;
    // 4-edge unroll: payload loads batched first for MLP
    for (; e + 3 < end; e += 4) {
        int4 p0 = g_epay[e];
        int4 p1 = g_epay[e + 1];
        int4 p2 = g_epay[e + 2];
        int4 p3 = g_epay[e + 3];
        const __half2* A0 = (const __half2*)(g_A + (size_t)p0.x * CCH);
        const __half2* A1 = (const __half2*)(g_A + (size_t)p1.x * CCH);
        const __half2* A2 = (const __half2*)(g_A + (size_t)p2.x * CCH);
        const __half2* A3 = (const __half2*)(g_A + (size_t)p3.x * CCH);
        __half2 hx0 = A0[lane], hy0 = A0[32 + lane];
        __half2 hx1 = A1[lane], hy1 = A1[32 + lane];
        __half2 hx2 = A2[lane], hy2 = A2[32 + lane];
        __half2 hx3 = A3[lane], hy3 = A3[32 + lane];
        {
            float2 x = __half22float2(hx0), y = __half22float2(hy0);
            float a = __int_as_float(p0.y), b = __int_as_float(p0.z);
            aR.x = fmaf(a, x.x, fmaf(-b, y.x, aR.x));
            aR.y = fmaf(a, x.y, fmaf(-b, y.y, aR.y));
            aI.x = fmaf(b, x.x, fmaf( a, y.x, aI.x));
            aI.y = fmaf(b, x.y, fmaf( a, y.y, aI.y));
        }
        {
            float2 x = __half22float2(hx1), y = __half22float2(hy1);
            float a = __int_as_float(p1.y), b = __int_as_float(p1.z);
            aR.x = fmaf(a, x.x, fmaf(-b, y.x, aR.x));
            aR.y = fmaf(a, x.y, fmaf(-b, y.y, aR.y));
            aI.x = fmaf(b, x.x, fmaf( a, y.x, aI.x));
            aI.y = fmaf(b, x.y, fmaf( a, y.y, aI.y));
        }
        {
            float2 x = __half22float2(hx2), y = __half22float2(hy2);
            float a = __int_as_float(p2.y), b = __int_as_float(p2.z);
            aR.x = fmaf(a, x.x, fmaf(-b, y.x, aR.x));
            aR.y = fmaf(a, x.y, fmaf(-b, y.y, aR.y));
            aI.x = fmaf(b, x.x, fmaf( a, y.x, aI.x));
            aI.y = fmaf(b, x.y, fmaf( a, y.y, aI.y));
        }
        {
            float2 x = __half22float2(hx3), y = __half22float2(hy3);
            float a = __int_as_float(p3.y), b = __int_as_float(p3.z);
            aR.x = fmaf(a, x.x, fmaf(-b, y.x, aR.x));
            aR.y = fmaf(a, x.y, fmaf(-b, y.y, aR.y));
            aI.x = fmaf(b, x.x, fmaf( a, y.x, aI.x));
            aI.y = fmaf(b, x.y, fmaf( a, y.y, aI.y));
        }
    }
    for (; e < end; e++) {
        int4 p = g_epay[e];
        const __half2* A = (const __half2*)(g_A + (size_t)p.x * CCH);
        float2 x = __half22float2(A[lane]);
        float2 y = __half22float2(A[32 + lane]);
        float a = __int_as_float(p.y), b = __int_as_float(p.z);
        aR.x = fmaf(a, x.x, fmaf(-b, y.x, aR.x));
        aR.y = fmaf(a, x.y, fmaf(-b, y.y, aR.y));
        aI.x = fmaf(b, x.x, fmaf( a, y.x, aI.x));
        aI.y = fmaf(b, x.y, fmaf( a, y.y, aI.y));
    }

    // complex ReLU gated on real part
    float2 hr, hi;
    hr.x = (aR.x >= 0.f) ? aR.x : 0.f;  hi.x = (aR.x >= 0.f) ? aI.x : 0.f;
    hr.y = (aR.y >= 0.f) ? aR.y : 0.f;  hi.y = (aR.y >= 0.f) ? aI.y : 0.f;
    *(float2*)&g_Hr[w * NF + lane * 2] = hr;
    *(float2*)&g_Hi[w * NF + lane * 2] = hi;
}

// ---------------- CBAM channel attention -------------------------------------
__global__ void zero_cmean_k() {
    if (threadIdx.x < CCH) g_cmean[threadIdx.x] = 0.f;
}

__global__ void chan_sum_k() {
    const int NPB = 512;
    int t = threadIdx.x;            // 256
    int c = t & 127;
    int half = t >> 7;
    int n0 = blockIdx.x * NPB;
    int n1 = min(n0 + NPB, NN);
    const float* src = (c < NF) ? g_Hr : g_Hi;
    int cc = c & (NF - 1);
    float s = 0.f;
    for (int n = n0 + half; n < n1; n += 2) s += src[n * NF + cc];
    __shared__ float sm[256];
    sm[t] = s;
    __syncthreads();
    if (t < 128) atomicAdd(&g_cmean[c], sm[t] + sm[t + 128]);
}

__global__ void ca_k(const float* __restrict__ w1, const float* __restrict__ w2) {
    __shared__ float avg[CCH];
    __shared__ float hid[8];
    int t = threadIdx.x;            // 128
    avg[t] = g_cmean[t] * (1.f / (float)NN);
    __syncthreads();
    if (t < 8) {
        float s = 0.f;
        #pragma unroll 4
        for (int c = 0; c < CCH; c++) s += w1[t * CCH + c] * avg[c];
        hid[t] = fmaxf(s, 0.f);
    }
    __syncthreads();
    float o = 0.f;
    #pragma unroll
    for (int r = 0; r < 8; r++) o += w2[t * 8 + r] * hid[r];
    g_ca[t] = 1.f / (1.f + expf(-o));
}

// ---------------- spatial stats (after CA scaling) ---------------------------
__global__ void sstat_k() {
    __shared__ float ca[CCH];
    if (threadIdx.x < CCH) ca[threadIdx.x] = g_ca[threadIdx.x];
    __syncthreads();
    int n = blockIdx.x * blockDim.x + threadIdx.x;
    if (n >= NN) return;
    float sum = 0.f, mx = -1e30f;
    const float4* hr = (const float4*)&g_Hr[n * NF];
    #pragma unroll
    for (int j = 0; j < 16; j++) {
        float4 v = hr[j];
        float a0 = v.x * ca[j*4+0], a1 = v.y * ca[j*4+1];
        float a2 = v.z * ca[j*4+2], a3 = v.w * ca[j*4+3];
        sum += a0 + a1 + a2 + a3;
        mx = fmaxf(mx, fmaxf(fmaxf(a0, a1), fmaxf(a2, a3)));
    }
    const float4* hi = (const float4*)&g_Hi[n * NF];
    #pragma unroll
    for (int j = 0; j < 16; j++) {
        float4 v = hi[j];
        float a0 = v.x * ca[64+j*4+0], a1 = v.y * ca[64+j*4+1];
        float a2 = v.z * ca[64+j*4+2], a3 = v.w * ca[64+j*4+3];
        sum += a0 + a1 + a2 + a3;
        mx = fmaxf(mx, fmaxf(fmaxf(a0, a1), fmaxf(a2, a3)));
    }
    g_smean[n] = sum * (1.f / (float)CCH);
    g_smax[n]  = mx;
}

// ---------------- spatial attention + final conv + log_softmax ---------------
__global__ void final_k(const float* __restrict__ sa_w,
                        const float* __restrict__ conv_w,
                        const float* __restrict__ conv_b,
                        float* __restrict__ out) {
    __shared__ float ca[CCH];
    __shared__ float cw[LABEL * CCH];
    __shared__ float cb[LABEL];
    __shared__ float sw[14];
    int t = threadIdx.x;
    if (t < CCH) ca[t] = g_ca[t];
    for (int idx = t; idx < LABEL * CCH; idx += blockDim.x) cw[idx] = conv_w[idx];
    if (t < LABEL) cb[t] = conv_b[t];
    if (t < 14) sw[t] = sa_w[t];
    __syncthreads();

    int n = blockIdx.x * blockDim.x + t;
    if (n >= NN) return;

    float s = 0.f;
    #pragma unroll
    for (int tap = 0; tap < 7; tap++) {
        int m = n - 3 + tap;
        if (m >= 0 && m < NN) s += sw[tap] * g_smean[m] + sw[7 + tap] * g_smax[m];
    }
    float sa = 1.f / (1.f + expf(-s));

    float acc[LABEL];
    #pragma unroll
    for (int l = 0; l < LABEL; l++) acc[l] = cb[l];

    const float* hr = &g_Hr[n * NF];
    const float* hi = &g_Hi[n * NF];
    #pragma unroll 4
    for (int c = 0; c < NF; c++) {
        float xv = hr[c] * ca[c] * sa;
        #pragma unroll
        for (int l = 0; l < LABEL; l++) acc[l] += cw[l * CCH + c] * xv;
    }
    #pragma unroll 4
    for (int c = 0; c < NF; c++) {
        float xv = hi[c] * ca[NF + c] * sa;
        #pragma unroll
        for (int l = 0; l < LABEL; l++) acc[l] += cw[l * CCH + NF + c] * xv;
    }

    float mx = acc[0];
    #pragma unroll
    for (int l = 1; l < LABEL; l++) mx = fmaxf(mx, acc[l]);
    float se = 0.f;
    #pragma unroll
    for (int l = 0; l < LABEL; l++) se += expf(acc[l] - mx);
    float lse = logf(se) + mx;
    #pragma unroll
    for (int l = 0; l < LABEL; l++) out[l * NN + n] = acc[l] - lse;
}

// ---------------- launch sequence --------------------------------------------
extern "C" void kernel_launch(void* const* d_in, const int* in_sizes, int n_in,
                              void* d_out, int out_size) {
    const float* Xr    = (const float*)d_in[0];
    const float* Xi    = (const float*)d_in[1];
    const int*   rows  = (const int*)  d_in[2];
    const int*   cols  = (const int*)  d_in[3];
    const float* vr    = (const float*)d_in[4];
    const float* vi    = (const float*)d_in[5];
    const float* w0    = (const float*)d_in[6];
    const float* b0    = (const float*)d_in[7];
    const float* w1    = (const float*)d_in[8];
    const float* b1    = (const float*)d_in[9];
    const float* w2    = (const float*)d_in[10];
    const float* b2    = (const float*)d_in[11];
    const float* caw1  = (const float*)d_in[12];
    const float* caw2  = (const float*)d_in[13];
    const float* saw   = (const float*)d_in[14];
    const float* convw = (const float*)d_in[15];
    const float* convb = (const float*)d_in[16];
    float* out = (float*)d_out;

    const dim3 gemm_grid((NN + 127) / 128, 6);
    const int edge_blocks   = (TOTE + 255) / 256;
    const int gather_blocks = (NN * 32 + 255) / 256;
    const int node_blocks   = (NN + 255) / 256;

    // ---- CSR build (reused by all 3 layers) ----
    zero_cnt_k<<<(NN + 256) / 256, 256>>>();
    hist_k<<<edge_blocks, 256>>>(rows);
    scan_k<<<1, 1024>>>();
    scatter_k<<<edge_blocks, 256>>>(rows, cols, vr, vi);

    // ---- layer 0 (FIN=128, inputs from d_in) ----
    gemm_k<INC, false><<<gemm_grid, 256>>>(Xr, Xi, w0);
    spmm_gather_k<<<gather_blocks, 256>>>(b0);

    // ---- layer 1 ----
    gemm_k<NF, true><<<gemm_grid, 256>>>(nullptr, nullptr, w1);
    spmm_gather_k<<<gather_blocks, 256>>>(b1);

    // ---- layer 2 ----
    gemm_k<NF, true><<<gemm_grid, 256>>>(nullptr, nullptr, w2);
    spmm_gather_k<<<gather_blocks, 256>>>(b2);

    // ---- CBAM + head ----
    zero_cmean_k<<<1, 128>>>();
    chan_sum_k<<<(NN + 511) / 512, 256>>>();
    ca_k<<<1, 128>>>(caw1, caw2);
    sstat_k<<<node_blocks, 256>>>();
    final_k<<<node_blocks, 256>>>(saw, convw, convb, out);
}

// round 5
// speedup vs baseline: 1.6423x; 1.0519x over previous
#include <cuda_runtime.h>
#include <cuda_bf16.h>
#include <cuda_fp16.h>
#include <math.h>

#define NN    50000
#define EDG   800000
#define K1    3
#define INC   128
#define NF    64
#define CCH   128   // 2*NF
#define LABEL 10
#define TOTE  (K1*EDG)

// packed fp32x2 FMA (Blackwell FFMA2; ptxas never emits it from C++)
#define FMA2(d, a, b) \
    asm("fma.rn.f32x2 %0, %1, %2, %0;" : "+l"(d) : "l"(a), "l"(b))
#define PACKF2(d, lo, hi) \
    asm("mov.b64 %0, {%1, %2};" : "=l"(d) : "f"(lo), "f"(hi))
#define UNPACKF2(lo, hi, s) \
    asm("mov.b64 {%0, %1}, %2;" : "=f"(lo), "=f"(hi) : "l"(s))
#define PACKH2(d, lo, hi) \
    asm("cvt.rn.f16x2.f32 %0, %1, %2;" : "=r"(d) : "f"(hi), "f"(lo))

// ---------------- scratch (device globals; no allocs allowed) ----------------
// A layout per (k,node): 16 groups of 16B; group g = (r_{4g..4g+3}, i_{4g..4g+3}) fp16
__device__ __half g_A[(size_t)K1 * NN * CCH];
__device__ float g_Hr[NN * NF];               // hidden (real, post-activation)
__device__ float g_Hi[NN * NF];
__device__ int   g_cnt[NN + 1];
__device__ int   g_off[NN + 1];
__device__ int   g_cursor[NN];
__device__ int2  g_epay[TOTE];                // (k*NN+c, half2(vr,vi))
__device__ float g_cmean[CCH];
__device__ float g_ca[CCH];
__device__ float g_smean[NN];
__device__ float g_smax[NN];

// ---------------- GEMM: interleaved fp16 A output -----------------------------
// grid.x tiles 128 rows; grid.y = 6 (k*2 + ri). block = 256. f32x2 inner loop.
template<int FIN, bool FROMG>
__global__ void gemm_k(const float* __restrict__ HrIn, const float* __restrict__ HiIn,
                       const float* __restrict__ Wall) {
    const int z  = blockIdx.y;
    const int k  = z >> 1, ri = z & 1;
    const float* H;
    if (FROMG) H = ri ? g_Hi : g_Hr;
    else       H = ri ? HiIn : HrIn;
    const float* W = Wall + k * FIN * NF;
    char* OutB = (char*)g_A + (size_t)k * NN * 256;   // 256B per node row

    const int row0 = blockIdx.x * 128;
    const int tid  = threadIdx.x;
    const int tx   = tid & 7;       // col group: cols tx*8 .. tx*8+7
    const int ty   = tid >> 3;      // 0..31 ; rows ty + j*32

    __shared__ float Hs[128][33];
    __shared__ float Ws[32][64];

    unsigned long long acc[4][4];   // [row j][col pair]
    #pragma unroll
    for (int j = 0; j < 4; j++)
        #pragma unroll
        for (int p = 0; p < 4; p++) acc[j][p] = 0ull;

    for (int kc = 0; kc < FIN; kc += 32) {
        for (int idx = tid; idx < 128 * 32; idx += 256) {
            int r = idx >> 5, i = idx & 31;
            int gr = row0 + r;
            Hs[r][i] = (gr < NN) ? H[gr * FIN + kc + i] : 0.f;
        }
        for (int idx = tid; idx < 32 * 64; idx += 256) {
            int i = idx >> 6, c = idx & 63;
            Ws[i][c] = W[(kc + i) * NF + c];
        }
        __syncthreads();
        #pragma unroll 8
        for (int i = 0; i < 32; i++) {
            longlong2 w01 = *(const longlong2*)&Ws[i][tx * 8];
            longlong2 w23 = *(const longlong2*)&Ws[i][tx * 8 + 4];
            #pragma unroll
            for (int j = 0; j < 4; j++) {
                float h = Hs[ty + j * 32][i];
                unsigned long long hh;
                PACKF2(hh, h, h);
                FMA2(acc[j][0], hh, (unsigned long long)w01.x);
                FMA2(acc[j][1], hh, (unsigned long long)w01.y);
                FMA2(acc[j][2], hh, (unsigned long long)w23.x);
                FMA2(acc[j][3], hh, (unsigned long long)w23.y);
            }
        }
        __syncthreads();
    }
    #pragma unroll
    for (int j = 0; j < 4; j++) {
        int gr = row0 + ty + j * 32;
        if (gr < NN) {
            unsigned s0, s1, s2, s3;
            float lo, hi;
            UNPACKF2(lo, hi, acc[j][0]); PACKH2(s0, lo, hi);
            UNPACKF2(lo, hi, acc[j][1]); PACKH2(s1, lo, hi);
            UNPACKF2(lo, hi, acc[j][2]); PACKH2(s2, lo, hi);
            UNPACKF2(lo, hi, acc[j][3]); PACKH2(s3, lo, hi);
            // group 2tx at byte 32tx; real slot +0, imag slot +8; group 2tx+1 at +16
            char* base = OutB + (size_t)gr * 256 + 32 * tx + ri * 8;
            *(uint2*)(base)      = make_uint2(s0, s1);   // cols 8tx..8tx+3
            *(uint2*)(base + 16) = make_uint2(s2, s3);   // cols 8tx+4..8tx+7
        }
    }
}

// ---------------- CSR build (once per launch; topology shared by 3 layers) ---
__global__ void zero_cnt_k() {
    int i = blockIdx.x * 256 + threadIdx.x;
    if (i <= NN) g_cnt[i] = 0;
}

__global__ void hist_k(const int* __restrict__ rows) {
    int e = blockIdx.x * 256 + threadIdx.x;
    if (e < TOTE) atomicAdd(&g_cnt[rows[e]], 1);
}

// one-block exclusive scan: 1024 threads x 49-element chunks
__global__ void scan_k() {
    const int CHUNK = 49;                 // 1024*49 = 50176 >= NN+1
    __shared__ int sm[1024];
    int t = threadIdx.x;
    int base = t * CHUNK;
    int sum = 0;
    #pragma unroll
    for (int i = 0; i < CHUNK; i++) {
        int idx = base + i;
        if (idx < NN) sum += g_cnt[idx];
    }
    sm[t] = sum;
    __syncthreads();
    #pragma unroll
    for (int d = 1; d < 1024; d <<= 1) {
        int v = (t >= d) ? sm[t - d] : 0;
        __syncthreads();
        sm[t] += v;
        __syncthreads();
    }
    int run = (t == 0) ? 0 : sm[t - 1];
    #pragma unroll
    for (int i = 0; i < CHUNK; i++) {
        int idx = base + i;
        if (idx < NN) {
            g_off[idx]    = run;
            g_cursor[idx] = run;
            run += g_cnt[idx];
        } else if (idx == NN) {
            g_off[NN] = run;
        }
    }
}

__global__ void scatter_k(const int* __restrict__ rows, const int* __restrict__ cols,
                          const float* __restrict__ vr, const float* __restrict__ vi) {
    int e = blockIdx.x * 256 + threadIdx.x;
    if (e >= TOTE) return;
    int k = (e >= 2 * EDG) ? 2 : (e >= EDG) ? 1 : 0;   // no integer divide
    int r = rows[e];
    int pos = atomicAdd(&g_cursor[r], 1);
    __half2 hv = __floats2half2_rn(vr[e], vi[e]);
    int2 pay;
    pay.x = k * NN + cols[e];
    pay.y = *(int*)&hv;
    g_epay[pos] = pay;
}

// ---------------- SpMM gather: half-warp per edge, 1 LDG.128 per edge --------
__global__ void spmm_gather_k(const float* __restrict__ bias) {
    int w    = (blockIdx.x * 256 + threadIdx.x) >> 5;
    int lane = threadIdx.x & 31;
    if (w >= NN) return;
    int half_id = lane >> 4;     // which edge of the pair
    int l16     = lane & 15;     // channel group (4 channels)

    float aR0=0.f, aR1=0.f, aR2=0.f, aR3=0.f;
    float aI0=0.f, aI1=0.f, aI2=0.f, aI3=0.f;

    const char* Ab = (const char*)g_A;
    int beg = g_off[w], end = g_off[w + 1];
    #pragma unroll 4
    for (int e = beg; e < end; e += 2) {
        int ee = e + half_id;
        int ec = min(ee, end - 1);
        int2 p = g_epay[ec];
        float2 vv = __half22float2(*(const __half2*)&p.y);
        float a = (ee < end) ? vv.x : 0.f;
        float b = (ee < end) ? vv.y : 0.f;
        uint4 q = *(const uint4*)(Ab + (((unsigned)p.x) << 8) + l16 * 16);
        float2 r01 = __half22float2(*(const __half2*)&q.x);
        float2 r23 = __half22float2(*(const __half2*)&q.y);
        float2 i01 = __half22float2(*(const __half2*)&q.z);
        float2 i23 = __half22float2(*(const __half2*)&q.w);
        aR0 = fmaf(a, r01.x, fmaf(-b, i01.x, aR0));
        aI0 = fmaf(b, r01.x, fmaf( a, i01.x, aI0));
        aR1 = fmaf(a, r01.y, fmaf(-b, i01.y, aR1));
        aI1 = fmaf(b, r01.y, fmaf( a, i01.y, aI1));
        aR2 = fmaf(a, r23.x, fmaf(-b, i23.x, aR2));
        aI2 = fmaf(b, r23.x, fmaf( a, i23.x, aI2));
        aR3 = fmaf(a, r23.y, fmaf(-b, i23.y, aR3));
        aI3 = fmaf(b, r23.y, fmaf( a, i23.y, aI3));
    }
    // combine the two half-warps' edge partials
    aR0 += __shfl_xor_sync(0xffffffffu, aR0, 16);
    aR1 += __shfl_xor_sync(0xffffffffu, aR1, 16);
    aR2 += __shfl_xor_sync(0xffffffffu, aR2, 16);
    aR3 += __shfl_xor_sync(0xffffffffu, aR3, 16);
    aI0 += __shfl_xor_sync(0xffffffffu, aI0, 16);
    aI1 += __shfl_xor_sync(0xffffffffu, aI1, 16);
    aI2 += __shfl_xor_sync(0xffffffffu, aI2, 16);
    aI3 += __shfl_xor_sync(0xffffffffu, aI3, 16);

    if (half_id == 0) {
        float4 bv = *(const float4*)&bias[l16 * 4];
        float r0 = aR0 + bv.x, r1 = aR1 + bv.y, r2 = aR2 + bv.z, r3 = aR3 + bv.w;
        float i0 = aI0 + bv.x, i1 = aI1 + bv.y, i2 = aI2 + bv.z, i3 = aI3 + bv.w;
        float4 hr, hi;
        hr.x = (r0 >= 0.f) ? r0 : 0.f;  hi.x = (r0 >= 0.f) ? i0 : 0.f;
        hr.y = (r1 >= 0.f) ? r1 : 0.f;  hi.y = (r1 >= 0.f) ? i1 : 0.f;
        hr.z = (r2 >= 0.f) ? r2 : 0.f;  hi.z = (r2 >= 0.f) ? i2 : 0.f;
        hr.w = (r3 >= 0.f) ? r3 : 0.f;  hi.w = (r3 >= 0.f) ? i3 : 0.f;
        *(float4*)&g_Hr[w * NF + l16 * 4] = hr;
        *(float4*)&g_Hi[w * NF + l16 * 4] = hi;
    }
}

// ---------------- CBAM channel attention -------------------------------------
__global__ void zero_cmean_k() {
    if (threadIdx.x < CCH) g_cmean[threadIdx.x] = 0.f;
}

__global__ void chan_sum_k() {
    const int NPB = 512;
    int t = threadIdx.x;            // 256
    int c = t & 127;
    int half = t >> 7;
    int n0 = blockIdx.x * NPB;
    int n1 = min(n0 + NPB, NN);
    const float* src = (c < NF) ? g_Hr : g_Hi;
    int cc = c & (NF - 1);
    float s = 0.f;
    for (int n = n0 + half; n < n1; n += 2) s += src[n * NF + cc];
    __shared__ float sm[256];
    sm[t] = s;
    __syncthreads();
    if (t < 128) atomicAdd(&g_cmean[c], sm[t] + sm[t + 128]);
}

__global__ void ca_k(const float* __restrict__ w1, const float* __restrict__ w2) {
    __shared__ float avg[CCH];
    __shared__ float hid[8];
    int t = threadIdx.x;            // 128
    avg[t] = g_cmean[t] * (1.f / (float)NN);
    __syncthreads();
    if (t < 8) {
        float s = 0.f;
        #pragma unroll 4
        for (int c = 0; c < CCH; c++) s += w1[t * CCH + c] * avg[c];
        hid[t] = fmaxf(s, 0.f);
    }
    __syncthreads();
    float o = 0.f;
    #pragma unroll
    for (int r = 0; r < 8; r++) o += w2[t * 8 + r] * hid[r];
    g_ca[t] = 1.f / (1.f + expf(-o));
}

// ---------------- spatial stats (after CA scaling) ---------------------------
__global__ void sstat_k() {
    __shared__ float ca[CCH];
    if (threadIdx.x < CCH) ca[threadIdx.x] = g_ca[threadIdx.x];
    __syncthreads();
    int n = blockIdx.x * blockDim.x + threadIdx.x;
    if (n >= NN) return;
    float sum = 0.f, mx = -1e30f;
    const float4* hr = (const float4*)&g_Hr[n * NF];
    #pragma unroll
    for (int j = 0; j < 16; j++) {
        float4 v = hr[j];
        float a0 = v.x * ca[j*4+0], a1 = v.y * ca[j*4+1];
        float a2 = v.z * ca[j*4+2], a3 = v.w * ca[j*4+3];
        sum += a0 + a1 + a2 + a3;
        mx = fmaxf(mx, fmaxf(fmaxf(a0, a1), fmaxf(a2, a3)));
    }
    const float4* hi = (const float4*)&g_Hi[n * NF];
    #pragma unroll
    for (int j = 0; j < 16; j++) {
        float4 v = hi[j];
        float a0 = v.x * ca[64+j*4+0], a1 = v.y * ca[64+j*4+1];
        float a2 = v.z * ca[64+j*4+2], a3 = v.w * ca[64+j*4+3];
        sum += a0 + a1 + a2 + a3;
        mx = fmaxf(mx, fmaxf(fmaxf(a0, a1), fmaxf(a2, a3)));
    }
    g_smean[n] = sum * (1.f / (float)CCH);
    g_smax[n]  = mx;
}

// ---------------- spatial attention + final conv + log_softmax ---------------
__global__ void final_k(const float* __restrict__ sa_w,
                        const float* __restrict__ conv_w,
                        const float* __restrict__ conv_b,
                        float* __restrict__ out) {
    __shared__ float ca[CCH];
    __shared__ float cw[LABEL * CCH];
    __shared__ float cb[LABEL];
    __shared__ float sw[14];
    int t = threadIdx.x;
    if (t < CCH) ca[t] = g_ca[t];
    for (int idx = t; idx < LABEL * CCH; idx += blockDim.x) cw[idx] = conv_w[idx];
    if (t < LABEL) cb[t] = conv_b[t];
    if (t < 14) sw[t] = sa_w[t];
    __syncthreads();

    int n = blockIdx.x * blockDim.x + t;
    if (n >= NN) return;

    float s = 0.f;
    #pragma unroll
    for (int tap = 0; tap < 7; tap++) {
        int m = n - 3 + tap;
        if (m >= 0 && m < NN) s += sw[tap] * g_smean[m] + sw[7 + tap] * g_smax[m];
    }
    float sa = 1.f / (1.f + expf(-s));

    float acc[LABEL];
    #pragma unroll
    for (int l = 0; l < LABEL; l++) acc[l] = cb[l];

    const float* hr = &g_Hr[n * NF];
    const float* hi = &g_Hi[n * NF];
    #pragma unroll 4
    for (int c = 0; c < NF; c++) {
        float xv = hr[c] * ca[c] * sa;
        #pragma unroll
        for (int l = 0; l < LABEL; l++) acc[l] += cw[l * CCH + c] * xv;
    }
    #pragma unroll 4
    for (int c = 0; c < NF; c++) {
        float xv = hi[c] * ca[NF + c] * sa;
        #pragma unroll
        for (int l = 0; l < LABEL; l++) acc[l] += cw[l * CCH + NF + c] * xv;
    }

    float mx = acc[0];
    #pragma unroll
    for (int l = 1; l < LABEL; l++) mx = fmaxf(mx, acc[l]);
    float se = 0.f;
    #pragma unroll
    for (int l = 0; l < LABEL; l++) se += expf(acc[l] - mx);
    float lse = logf(se) + mx;
    #pragma unroll
    for (int l = 0; l < LABEL; l++) out[l * NN + n] = acc[l] - lse;
}

// ---------------- launch sequence --------------------------------------------
extern "C" void kernel_launch(void* const* d_in, const int* in_sizes, int n_in,
                              void* d_out, int out_size) {
    const float* Xr    = (const float*)d_in[0];
    const float* Xi    = (const float*)d_in[1];
    const int*   rows  = (const int*)  d_in[2];
    const int*   cols  = (const int*)  d_in[3];
    const float* vr    = (const float*)d_in[4];
    const float* vi    = (const float*)d_in[5];
    const float* w0    = (const float*)d_in[6];
    const float* b0    = (const float*)d_in[7];
    const float* w1    = (const float*)d_in[8];
    const float* b1    = (const float*)d_in[9];
    const float* w2    = (const float*)d_in[10];
    const float* b2    = (const float*)d_in[11];
    const float* caw1  = (const float*)d_in[12];
    const float* caw2  = (const float*)d_in[13];
    const float* saw   = (const float*)d_in[14];
    const float* convw = (const float*)d_in[15];
    const float* convb = (const float*)d_in[16];
    float* out = (float*)d_out;

    const dim3 gemm_grid((NN + 127) / 128, 6);
    const int edge_blocks   = (TOTE + 255) / 256;
    const int gather_blocks = (NN * 32 + 255) / 256;
    const int node_blocks   = (NN + 255) / 256;

    // ---- CSR build (reused by all 3 layers) ----
    zero_cnt_k<<<(NN + 256) / 256, 256>>>();
    hist_k<<<edge_blocks, 256>>>(rows);
    scan_k<<<1, 1024>>>();
    scatter_k<<<edge_blocks, 256>>>(rows, cols, vr, vi);

    // ---- layer 0 (FIN=128, inputs from d_in) ----
    gemm_k<INC, false><<<gemm_grid, 256>>>(Xr, Xi, w0);
    spmm_gather_k<<<gather_blocks, 256>>>(b0);

    // ---- layer 1 ----
    gemm_k<NF, true><<<gemm_grid, 256>>>(nullptr, nullptr, w1);
    spmm_gather_k<<<gather_blocks, 256>>>(b1);

    // ---- layer 2 ----
    gemm_k<NF, true><<<gemm_grid, 256>>>(nullptr, nullptr, w2);
    spmm_gather_k<<<gather_blocks, 256>>>(b2);

    // ---- CBAM + head ----
    zero_cmean_k<<<1, 128>>>();
    chan_sum_k<<<(NN + 511) / 512, 256>>>();
    ca_k<<<1, 128>>>(caw1, caw2);
    sstat_k<<<node_blocks, 256>>>();
    final_k<<<node_blocks, 256>>>(saw, convw, convb, out);
}

// round 10
// speedup vs baseline: 1.6947x; 1.0319x over previous
#include <cuda_runtime.h>
#include <cuda_bf16.h>
#include <cuda_fp16.h>
#include <math.h>

#define NN    50000
#define EDG   800000
#define K1    3
#define INC   128
#define NF    64
#define CCH   128   // 2*NF
#define LABEL 10
#define TOTE  (K1*EDG)

// packed fp32x2 FMA (Blackwell FFMA2; ptxas never emits it from C++)
#define FMA2(d, a, b) \
    asm("fma.rn.f32x2 %0, %1, %2, %0;" : "+l"(d) : "l"(a), "l"(b))
#define PACKF2(d, lo, hi) \
    asm("mov.b64 %0, {%1, %2};" : "=l"(d) : "f"(lo), "f"(hi))
#define UNPACKF2(lo, hi, s) \
    asm("mov.b64 {%0, %1}, %2;" : "=f"(lo), "=f"(hi) : "l"(s))
#define PACKH2(d, lo, hi) \
    asm("cvt.rn.f16x2.f32 %0, %1, %2;" : "=r"(d) : "f"(hi), "f"(lo))

// ---------------- scratch (device globals; no allocs allowed) ----------------
// A layout per (k,node): 16 groups of 16B; group g = (r_{4g..4g+3}, i_{4g..4g+3}) fp16
__device__ __half g_A[(size_t)K1 * NN * CCH];
__device__ float g_Hr[NN * NF];               // hidden (real, post-activation)
__device__ float g_Hi[NN * NF];
__device__ int   g_cnt[NN + 1];               // zero-init at load; re-zeroed by scatter_k
__device__ int   g_off[NN + 1];
__device__ int   g_cursor[NN];
__device__ int2  g_epay[TOTE];                // (k*NN+c, half2(vr,vi))
__device__ float g_cmean[CCH];
__device__ float g_ca[CCH];
__device__ float g_smean[NN];
__device__ float g_smax[NN];

// ---------------- GEMM (FFMA2, fp32 math): interleaved fp16 A output ---------
// grid.x tiles 128 rows; grid.y = 6 (k*2 + ri). block = 256.
template<int FIN, bool FROMG>
__global__ void gemm_k(const float* __restrict__ HrIn, const float* __restrict__ HiIn,
                       const float* __restrict__ Wall) {
    const int z  = blockIdx.y;
    const int k  = z >> 1, ri = z & 1;
    const float* H;
    if (FROMG) H = ri ? g_Hi : g_Hr;
    else       H = ri ? HiIn : HrIn;
    const float* W = Wall + k * FIN * NF;
    char* OutB = (char*)g_A + (size_t)k * NN * 256;   // 256B per node row

    const int row0 = blockIdx.x * 128;
    const int tid  = threadIdx.x;
    const int tx   = tid & 7;       // col group: cols tx*8 .. tx*8+7
    const int ty   = tid >> 3;      // 0..31 ; rows ty + j*32

    __shared__ float Hs[128][33];
    __shared__ float Ws[32][64];

    unsigned long long acc[4][4];   // [row j][col pair]
    #pragma unroll
    for (int j = 0; j < 4; j++)
        #pragma unroll
        for (int p = 0; p < 4; p++) acc[j][p] = 0ull;

    for (int kc = 0; kc < FIN; kc += 32) {
        for (int idx = tid; idx < 128 * 32; idx += 256) {
            int r = idx >> 5, i = idx & 31;
            int gr = row0 + r;
            Hs[r][i] = (gr < NN) ? H[gr * FIN + kc + i] : 0.f;
        }
        for (int idx = tid; idx < 32 * 64; idx += 256) {
            int i = idx >> 6, c = idx & 63;
            Ws[i][c] = W[(kc + i) * NF + c];
        }
        __syncthreads();
        #pragma unroll 8
        for (int i = 0; i < 32; i++) {
            longlong2 w01 = *(const longlong2*)&Ws[i][tx * 8];
            longlong2 w23 = *(const longlong2*)&Ws[i][tx * 8 + 4];
            #pragma unroll
            for (int j = 0; j < 4; j++) {
                float h = Hs[ty + j * 32][i];
                unsigned long long hh;
                PACKF2(hh, h, h);
                FMA2(acc[j][0], hh, (unsigned long long)w01.x);
                FMA2(acc[j][1], hh, (unsigned long long)w01.y);
                FMA2(acc[j][2], hh, (unsigned long long)w23.x);
                FMA2(acc[j][3], hh, (unsigned long long)w23.y);
            }
        }
        __syncthreads();
    }
    #pragma unroll
    for (int j = 0; j < 4; j++) {
        int gr = row0 + ty + j * 32;
        if (gr < NN) {
            unsigned s0, s1, s2, s3;
            float lo, hi;
            UNPACKF2(lo, hi, acc[j][0]); PACKH2(s0, lo, hi);
            UNPACKF2(lo, hi, acc[j][1]); PACKH2(s1, lo, hi);
            UNPACKF2(lo, hi, acc[j][2]); PACKH2(s2, lo, hi);
            UNPACKF2(lo, hi, acc[j][3]); PACKH2(s3, lo, hi);
            // group 2tx at byte 32tx; real slot +0, imag slot +8; group 2tx+1 at +16
            char* base = OutB + (size_t)gr * 256 + 32 * tx + ri * 8;
            *(uint2*)(base)      = make_uint2(s0, s1);   // cols 8tx..8tx+3
            *(uint2*)(base + 16) = make_uint2(s2, s3);   // cols 8tx+4..8tx+7
        }
    }
}

// ---------------- CSR build (once per launch; topology shared by 3 layers) ---
__global__ void hist_k(const int* __restrict__ rows) {
    int e = blockIdx.x * 256 + threadIdx.x;
    if (e < TOTE) atomicAdd(&g_cnt[rows[e]], 1);
}

// one-block exclusive scan: 1024 threads x 49-element chunks
__global__ void scan_k() {
    const int CHUNK = 49;                 // 1024*49 = 50176 >= NN+1
    __shared__ int sm[1024];
    int t = threadIdx.x;
    int base = t * CHUNK;
    int sum = 0;
    #pragma unroll
    for (int i = 0; i < CHUNK; i++) {
        int idx = base + i;
        if (idx < NN) sum += g_cnt[idx];
    }
    sm[t] = sum;
    __syncthreads();
    #pragma unroll
    for (int d = 1; d < 1024; d <<= 1) {
        int v = (t >= d) ? sm[t - d] : 0;
        __syncthreads();
        sm[t] += v;
        __syncthreads();
    }
    int run = (t == 0) ? 0 : sm[t - 1];
    #pragma unroll
    for (int i = 0; i < CHUNK; i++) {
        int idx = base + i;
        if (idx < NN) {
            g_off[idx]    = run;
            g_cursor[idx] = run;
            run += g_cnt[idx];
        } else if (idx == NN) {
            g_off[NN] = run;
        }
    }
}

__global__ void scatter_k(const int* __restrict__ rows, const int* __restrict__ cols,
                          const float* __restrict__ vr, const float* __restrict__ vi) {
    int e = blockIdx.x * 256 + threadIdx.x;
    if (e <= NN) g_cnt[e] = 0;            // re-zero for next graph replay
    if (e >= TOTE) return;
    int k = (e >= 2 * EDG) ? 2 : (e >= EDG) ? 1 : 0;
    int r = rows[e];
    int pos = atomicAdd(&g_cursor[r], 1);
    __half2 hv = __floats2half2_rn(vr[e], vi[e]);
    int2 pay;
    pay.x = k * NN + cols[e];
    pay.y = *(int*)&hv;
    g_epay[pos] = pay;
}

// ---------------- SpMM gather: half-warp per edge, high-MLP main loop --------
// Main loop: 8 edges per warp iteration; half h owns edges e+4h..e+4h+3 with
// unpredicated loads (4 payload LDG.64 + 4 A LDG.128 batched). Guarded tail.
__global__ void spmm_gather_k(const float* __restrict__ bias) {
    int w    = (blockIdx.x * 256 + threadIdx.x) >> 5;
    int lane = threadIdx.x & 31;
    if (w >= NN) return;
    int half_id = lane >> 4;     // edge subgroup
    int l16     = lane & 15;     // channel group (4 channels)

    float aR0=0.f, aR1=0.f, aR2=0.f, aR3=0.f;
    float aI0=0.f, aI1=0.f, aI2=0.f, aI3=0.f;

    const char* Ab = (const char*)g_A + l16 * 16;
    int beg = g_off[w], end = g_off[w + 1];
    int e = beg;

    for (; e + 8 <= end; e += 8) {
        int b4 = e + half_id * 4;
        int2 p0 = g_epay[b4 + 0];
        int2 p1 = g_epay[b4 + 1];
        int2 p2 = g_epay[b4 + 2];
        int2 p3 = g_epay[b4 + 3];
        uint4 q0 = *(const uint4*)(Ab + (((unsigned)p0.x) << 8));
        uint4 q1 = *(const uint4*)(Ab + (((unsigned)p1.x) << 8));
        uint4 q2 = *(const uint4*)(Ab + (((unsigned)p2.x) << 8));
        uint4 q3 = *(const uint4*)(Ab + (((unsigned)p3.x) << 8));
        {
            float2 vv = __half22float2(*(const __half2*)&p0.y);
            float2 r01 = __half22float2(*(const __half2*)&q0.x);
            float2 r23 = __half22float2(*(const __half2*)&q0.y);
            float2 i01 = __half22float2(*(const __half2*)&q0.z);
            float2 i23 = __half22float2(*(const __half2*)&q0.w);
            float a = vv.x, b = vv.y;
            aR0 = fmaf(a, r01.x, fmaf(-b, i01.x, aR0));
            aI0 = fmaf(b, r01.x, fmaf( a, i01.x, aI0));
            aR1 = fmaf(a, r01.y, fmaf(-b, i01.y, aR1));
            aI1 = fmaf(b, r01.y, fmaf( a, i01.y, aI1));
            aR2 = fmaf(a, r23.x, fmaf(-b, i23.x, aR2));
            aI2 = fmaf(b, r23.x, fmaf( a, i23.x, aI2));
            aR3 = fmaf(a, r23.y, fmaf(-b, i23.y, aR3));
            aI3 = fmaf(b, r23.y, fmaf( a, i23.y, aI3));
        }
        {
            float2 vv = __half22float2(*(const __half2*)&p1.y);
            float2 r01 = __half22float2(*(const __half2*)&q1.x);
            float2 r23 = __half22float2(*(const __half2*)&q1.y);
            float2 i01 = __half22float2(*(const __half2*)&q1.z);
            float2 i23 = __half22float2(*(const __half2*)&q1.w);
            float a = vv.x, b = vv.y;
            aR0 = fmaf(a, r01.x, fmaf(-b, i01.x, aR0));
            aI0 = fmaf(b, r01.x, fmaf( a, i01.x, aI0));
            aR1 = fmaf(a, r01.y, fmaf(-b, i01.y, aR1));
            aI1 = fmaf(b, r01.y, fmaf( a, i01.y, aI1));
            aR2 = fmaf(a, r23.x, fmaf(-b, i23.x, aR2));
            aI2 = fmaf(b, r23.x, fmaf( a, i23.x, aI2));
            aR3 = fmaf(a, r23.y, fmaf(-b, i23.y, aR3));
            aI3 = fmaf(b, r23.y, fmaf( a, i23.y, aI3));
        }
        {
            float2 vv = __half22float2(*(const __half2*)&p2.y);
            float2 r01 = __half22float2(*(const __half2*)&q2.x);
            float2 r23 = __half22float2(*(const __half2*)&q2.y);
            float2 i01 = __half22float2(*(const __half2*)&q2.z);
            float2 i23 = __half22float2(*(const __half2*)&q2.w);
            float a = vv.x, b = vv.y;
            aR0 = fmaf(a, r01.x, fmaf(-b, i01.x, aR0));
            aI0 = fmaf(b, r01.x, fmaf( a, i01.x, aI0));
            aR1 = fmaf(a, r01.y, fmaf(-b, i01.y, aR1));
            aI1 = fmaf(b, r01.y, fmaf( a, i01.y, aI1));
            aR2 = fmaf(a, r23.x, fmaf(-b, i23.x, aR2));
            aI2 = fmaf(b, r23.x, fmaf( a, i23.x, aI2));
            aR3 = fmaf(a, r23.y, fmaf(-b, i23.y, aR3));
            aI3 = fmaf(b, r23.y, fmaf( a, i23.y, aI3));
        }
        {
            float2 vv = __half22float2(*(const __half2*)&p3.y);
            float2 r01 = __half22float2(*(const __half2*)&q3.x);
            float2 r23 = __half22float2(*(const __half2*)&q3.y);
            float2 i01 = __half22float2(*(const __half2*)&q3.z);
            float2 i23 = __half22float2(*(const __half2*)&q3.w);
            float a = vv.x, b = vv.y;
            aR0 = fmaf(a, r01.x, fmaf(-b, i01.x, aR0));
            aI0 = fmaf(b, r01.x, fmaf( a, i01.x, aI0));
            aR1 = fmaf(a, r01.y, fmaf(-b, i01.y, aR1));
            aI1 = fmaf(b, r01.y, fmaf( a, i01.y, aI1));
            aR2 = fmaf(a, r23.x, fmaf(-b, i23.x, aR2));
            aI2 = fmaf(b, r23.x, fmaf( a, i23.x, aI2));
            aR3 = fmaf(a, r23.y, fmaf(-b, i23.y, aR3));
            aI3 = fmaf(b, r23.y, fmaf( a, i23.y, aI3));
        }
    }
    // tail: 2 edges per iteration, guarded
    for (; e < end; e += 2) {
        int ee = e + half_id;
        int ec = min(ee, end - 1);
        int2 p = g_epay[ec];
        float2 vv = __half22float2(*(const __half2*)&p.y);
        float a = (ee < end) ? vv.x : 0.f;
        float b = (ee < end) ? vv.y : 0.f;
        uint4 q = *(const uint4*)(Ab + (((unsigned)p.x) << 8));
        float2 r01 = __half22float2(*(const __half2*)&q.x);
        float2 r23 = __half22float2(*(const __half2*)&q.y);
        float2 i01 = __half22float2(*(const __half2*)&q.z);
        float2 i23 = __half22float2(*(const __half2*)&q.w);
        aR0 = fmaf(a, r01.x, fmaf(-b, i01.x, aR0));
        aI0 = fmaf(b, r01.x, fmaf( a, i01.x, aI0));
        aR1 = fmaf(a, r01.y, fmaf(-b, i01.y, aR1));
        aI1 = fmaf(b, r01.y, fmaf( a, i01.y, aI1));
        aR2 = fmaf(a, r23.x, fmaf(-b, i23.x, aR2));
        aI2 = fmaf(b, r23.x, fmaf( a, i23.x, aI2));
        aR3 = fmaf(a, r23.y, fmaf(-b, i23.y, aR3));
        aI3 = fmaf(b, r23.y, fmaf( a, i23.y, aI3));
    }

    // combine the two half-warps' partials
    aR0 += __shfl_xor_sync(0xffffffffu, aR0, 16);
    aR1 += __shfl_xor_sync(0xffffffffu, aR1, 16);
    aR2 += __shfl_xor_sync(0xffffffffu, aR2, 16);
    aR3 += __shfl_xor_sync(0xffffffffu, aR3, 16);
    aI0 += __shfl_xor_sync(0xffffffffu, aI0, 16);
    aI1 += __shfl_xor_sync(0xffffffffu, aI1, 16);
    aI2 += __shfl_xor_sync(0xffffffffu, aI2, 16);
    aI3 += __shfl_xor_sync(0xffffffffu, aI3, 16);

    if (half_id == 0) {
        float4 bv = *(const float4*)&bias[l16 * 4];
        float r0 = aR0 + bv.x, r1 = aR1 + bv.y, r2 = aR2 + bv.z, r3 = aR3 + bv.w;
        float i0 = aI0 + bv.x, i1 = aI1 + bv.y, i2 = aI2 + bv.z, i3 = aI3 + bv.w;
        float4 hr, hi;
        hr.x = (r0 >= 0.f) ? r0 : 0.f;  hi.x = (r0 >= 0.f) ? i0 : 0.f;
        hr.y = (r1 >= 0.f) ? r1 : 0.f;  hi.y = (r1 >= 0.f) ? i1 : 0.f;
        hr.z = (r2 >= 0.f) ? r2 : 0.f;  hi.z = (r2 >= 0.f) ? i2 : 0.f;
        hr.w = (r3 >= 0.f) ? r3 : 0.f;  hi.w = (r3 >= 0.f) ? i3 : 0.f;
        *(float4*)&g_Hr[w * NF + l16 * 4] = hr;
        *(float4*)&g_Hi[w * NF + l16 * 4] = hi;
    }
}

// ---------------- CBAM channel attention -------------------------------------
__global__ void zero_cmean_k() {
    if (threadIdx.x < CCH) g_cmean[threadIdx.x] = 0.f;
}

__global__ void chan_sum_k() {
    const int NPB = 512;
    int t = threadIdx.x;            // 256
    int c = t & 127;
    int half = t >> 7;
    int n0 = blockIdx.x * NPB;
    int n1 = min(n0 + NPB, NN);
    const float* src = (c < NF) ? g_Hr : g_Hi;
    int cc = c & (NF - 1);
    float s = 0.f;
    for (int n = n0 + half; n < n1; n += 2) s += src[n * NF + cc];
    __shared__ float sm[256];
    sm[t] = s;
    __syncthreads();
    if (t < 128) atomicAdd(&g_cmean[c], sm[t] + sm[t + 128]);
}

__global__ void ca_k(const float* __restrict__ w1, const float* __restrict__ w2) {
    __shared__ float avg[CCH];
    __shared__ float hid[8];
    int t = threadIdx.x;            // 128
    avg[t] = g_cmean[t] * (1.f / (float)NN);
    __syncthreads();
    if (t < 8) {
        float s = 0.f;
        #pragma unroll 4
        for (int c = 0; c < CCH; c++) s += w1[t * CCH + c] * avg[c];
        hid[t] = fmaxf(s, 0.f);
    }
    __syncthreads();
    float o = 0.f;
    #pragma unroll
    for (int r = 0; r < 8; r++) o += w2[t * 8 + r] * hid[r];
    g_ca[t] = 1.f / (1.f + expf(-o));
}

// ---------------- spatial stats (after CA scaling) ---------------------------
__global__ void sstat_k() {
    __shared__ float ca[CCH];
    if (threadIdx.x < CCH) ca[threadIdx.x] = g_ca[threadIdx.x];
    __syncthreads();
    int n = blockIdx.x * blockDim.x + threadIdx.x;
    if (n >= NN) return;
    float sum = 0.f, mx = -1e30f;
    const float4* hr = (const float4*)&g_Hr[n * NF];
    #pragma unroll
    for (int j = 0; j < 16; j++) {
        float4 v = hr[j];
        float a0 = v.x * ca[j*4+0], a1 = v.y * ca[j*4+1];
        float a2 = v.z * ca[j*4+2], a3 = v.w * ca[j*4+3];
        sum += a0 + a1 + a2 + a3;
        mx = fmaxf(mx, fmaxf(fmaxf(a0, a1), fmaxf(a2, a3)));
    }
    const float4* hi = (const float4*)&g_Hi[n * NF];
    #pragma unroll
    for (int j = 0; j < 16; j++) {
        float4 v = hi[j];
        float a0 = v.x * ca[64+j*4+0], a1 = v.y * ca[64+j*4+1];
        float a2 = v.z * ca[64+j*4+2], a3 = v.w * ca[64+j*4+3];
        sum += a0 + a1 + a2 + a3;
        mx = fmaxf(mx, fmaxf(fmaxf(a0, a1), fmaxf(a2, a3)));
    }
    g_smean[n] = sum * (1.f / (float)CCH);
    g_smax[n]  = mx;
}

// ---------------- spatial attention + final conv + log_softmax ---------------
__global__ void final_k(const float* __restrict__ sa_w,
                        const float* __restrict__ conv_w,
                        const float* __restrict__ conv_b,
                        float* __restrict__ out) {
    __shared__ float ca[CCH];
    __shared__ float cw[LABEL * CCH];
    __shared__ float cb[LABEL];
    __shared__ float sw[14];
    int t = threadIdx.x;
    if (t < CCH) ca[t] = g_ca[t];
    for (int idx = t; idx < LABEL * CCH; idx += blockDim.x) cw[idx] = conv_w[idx];
    if (t < LABEL) cb[t] = conv_b[t];
    if (t < 14) sw[t] = sa_w[t];
    __syncthreads();

    int n = blockIdx.x * blockDim.x + t;
    if (n >= NN) return;

    float s = 0.f;
    #pragma unroll
    for (int tap = 0; tap < 7; tap++) {
        int m = n - 3 + tap;
        if (m >= 0 && m < NN) s += sw[tap] * g_smean[m] + sw[7 + tap] * g_smax[m];
    }
    float sa = 1.f / (1.f + expf(-s));

    float acc[LABEL];
    #pragma unroll
    for (int l = 0; l < LABEL; l++) acc[l] = cb[l];

    const float* hr = &g_Hr[n * NF];
    const float* hi = &g_Hi[n * NF];
    #pragma unroll 4
    for (int c = 0; c < NF; c++) {
        float xv = hr[c] * ca[c] * sa;
        #pragma unroll
        for (int l = 0; l < LABEL; l++) acc[l] += cw[l * CCH + c] * xv;
    }
    #pragma unroll 4
    for (int c = 0; c < NF; c++) {
        float xv = hi[c] * ca[NF + c] * sa;
        #pragma unroll
        for (int l = 0; l < LABEL; l++) acc[l] += cw[l * CCH + NF + c] * xv;
    }

    float mx = acc[0];
    #pragma unroll
    for (int l = 1; l < LABEL; l++) mx = fmaxf(mx, acc[l]);
    float se = 0.f;
    #pragma unroll
    for (int l = 0; l < LABEL; l++) se += expf(acc[l] - mx);
    float lse = logf(se) + mx;
    #pragma unroll
    for (int l = 0; l < LABEL; l++) out[l * NN + n] = acc[l] - lse;
}

// ---------------- launch sequence --------------------------------------------
extern "C" void kernel_launch(void* const* d_in, const int* in_sizes, int n_in,
                              void* d_out, int out_size) {
    const float* Xr    = (const float*)d_in[0];
    const float* Xi    = (const float*)d_in[1];
    const int*   rows  = (const int*)  d_in[2];
    const int*   cols  = (const int*)  d_in[3];
    const float* vr    = (const float*)d_in[4];
    const float* vi    = (const float*)d_in[5];
    const float* w0    = (const float*)d_in[6];
    const float* b0    = (const float*)d_in[7];
    const float* w1    = (const float*)d_in[8];
    const float* b1    = (const float*)d_in[9];
    const float* w2    = (const float*)d_in[10];
    const float* b2    = (const float*)d_in[11];
    const float* caw1  = (const float*)d_in[12];
    const float* caw2  = (const float*)d_in[13];
    const float* saw   = (const float*)d_in[14];
    const float* convw = (const float*)d_in[15];
    const float* convb = (const float*)d_in[16];
    float* out = (float*)d_out;

    const dim3 gemm_grid((NN + 127) / 128, 6);
    const int edge_blocks   = (TOTE + 255) / 256;
    const int gather_blocks = (NN * 32 + 255) / 256;
    const int node_blocks   = (NN + 255) / 256;

    // ---- CSR build (reused by all 3 layers) ----
    hist_k<<<edge_blocks, 256>>>(rows);                       // launch 0
    scan_k<<<1, 1024>>>();                                    // launch 1
    scatter_k<<<edge_blocks, 256>>>(rows, cols, vr, vi);      // launch 2

    // ---- layer 0 (FIN=128, inputs from d_in) ----
    gemm_k<INC, false><<<gemm_grid, 256>>>(Xr, Xi, w0);       // launch 3 (profiled)
    spmm_gather_k<<<gather_blocks, 256>>>(b0);

    // ---- layer 1 ----
    gemm_k<NF, true><<<gemm_grid, 256>>>(nullptr, nullptr, w1);
    spmm_gather_k<<<gather_blocks, 256>>>(b1);

    // ---- layer 2 ----
    gemm_k<NF, true><<<gemm_grid, 256>>>(nullptr, nullptr, w2);
    spmm_gather_k<<<gather_blocks, 256>>>(b2);

    // ---- CBAM + head ----
    zero_cmean_k<<<1, 128>>>();
    chan_sum_k<<<(NN + 511) / 512, 256>>>();
    ca_k<<<1, 128>>>(caw1, caw2);
    sstat_k<<<node_blocks, 256>>>();
    final_k<<<node_blocks, 256>>>(saw, convw, convb, out);
}

// round 11
// speedup vs baseline: 1.7932x; 1.0581x over previous
#include <cuda_runtime.h>
#include <cuda_bf16.h>
#include <cuda_fp16.h>
#include <math.h>

#define NN    50000
#define EDG   800000
#define K1    3
#define INC   128
#define NF    64
#define CCH   128   // 2*NF
#define LABEL 10
#define TOTE  (K1*EDG)

// packed fp32x2 FMA (Blackwell FFMA2; ptxas never emits it from C++)
#define FMA2(d, a, b) \
    asm("fma.rn.f32x2 %0, %1, %2, %0;" : "+l"(d) : "l"(a), "l"(b))
#define PACKF2(d, lo, hi) \
    asm("mov.b64 %0, {%1, %2};" : "=l"(d) : "f"(lo), "f"(hi))
#define UNPACKF2(lo, hi, s) \
    asm("mov.b64 {%0, %1}, %2;" : "=f"(lo), "=f"(hi) : "l"(s))
#define PACKH2(d, lo, hi) \
    asm("cvt.rn.f16x2.f32 %0, %1, %2;" : "=r"(d) : "f"(hi), "f"(lo))

// ---------------- scratch (device globals; no allocs allowed) ----------------
// A layout per (k,node): 16 groups of 16B; group g = (r_{4g..4g+3}, i_{4g..4g+3}) fp16
__device__ __half g_A[(size_t)K1 * NN * CCH];
__device__ float g_Hr[NN * NF];               // hidden (real, post-activation)
__device__ float g_Hi[NN * NF];
__device__ int   g_cnt[NN + 1];               // zero-init at load; re-zeroed by scatter_k
__device__ int   g_off[NN + 1];
__device__ int   g_cursor[NN];
__device__ int2  g_epay[TOTE];                // (k*NN+c, half2(vr,vi))
__device__ float g_cmean[CCH];
__device__ float g_ca[CCH];
__device__ float g_smean[NN];
__device__ float g_smax[NN];

// ---------------- GEMM (FFMA2, fp32 math): interleaved fp16 A output ---------
// grid.x tiles 128 rows; grid.y = 6 (k*2 + ri). block = 256, >=4 blocks/SM.
// Hs stride 36 floats: 16B-aligned rows, conflict-free float4 row reads.
template<int FIN, bool FROMG>
__global__ void __launch_bounds__(256, 4)
gemm_k(const float* __restrict__ HrIn, const float* __restrict__ HiIn,
       const float* __restrict__ Wall) {
    const int z  = blockIdx.y;
    const int k  = z >> 1, ri = z & 1;
    const float* H;
    if (FROMG) H = ri ? g_Hi : g_Hr;
    else       H = ri ? HiIn : HrIn;
    const float* W = Wall + k * FIN * NF;
    char* OutB = (char*)g_A + (size_t)k * NN * 256;   // 256B per node row

    const int row0 = blockIdx.x * 128;
    const int tid  = threadIdx.x;
    const int tx   = tid & 7;       // col group: cols tx*8 .. tx*8+7
    const int ty   = tid >> 3;      // 0..31 ; rows ty + j*32

    __shared__ float Hs[128 * 36];  // stride 36
    __shared__ float Ws[32 * 64];

    unsigned long long acc[4][4];   // [row j][col pair]
    #pragma unroll
    for (int j = 0; j < 4; j++)
        #pragma unroll
        for (int p = 0; p < 4; p++) acc[j][p] = 0ull;

    for (int kc = 0; kc < FIN; kc += 32) {
        // H tile [128 x 32] via float4 (8 f4 per row)
        #pragma unroll
        for (int t = 0; t < 4; t++) {
            int idx = tid + t * 256;          // 0..1023
            int r   = idx >> 3, c4 = idx & 7;
            int gr  = row0 + r;
            float4 v = (gr < NN) ? *(const float4*)&H[(size_t)gr * FIN + kc + c4 * 4]
                                 : make_float4(0.f, 0.f, 0.f, 0.f);
            *(float4*)&Hs[r * 36 + c4 * 4] = v;
        }
        // W tile [32 x 64] via float4 (16 f4 per row)
        #pragma unroll
        for (int t = 0; t < 2; t++) {
            int idx = tid + t * 256;          // 0..511
            int i   = idx >> 4, c4 = idx & 15;
            *(float4*)&Ws[i * 64 + c4 * 4] = *(const float4*)&W[(kc + i) * NF + c4 * 4];
        }
        __syncthreads();
        #pragma unroll
        for (int i4 = 0; i4 < 8; i4++) {
            float4 h4[4];
            #pragma unroll
            for (int j = 0; j < 4; j++)
                h4[j] = *(const float4*)&Hs[(ty + j * 32) * 36 + i4 * 4];
            #pragma unroll
            for (int ii = 0; ii < 4; ii++) {
                const float* wrow = &Ws[(i4 * 4 + ii) * 64 + tx * 8];
                longlong2 w01 = *(const longlong2*)(wrow);
                longlong2 w23 = *(const longlong2*)(wrow + 4);
                #pragma unroll
                for (int j = 0; j < 4; j++) {
                    float h = (ii == 0) ? h4[j].x : (ii == 1) ? h4[j].y
                            : (ii == 2) ? h4[j].z : h4[j].w;
                    unsigned long long hh;
                    PACKF2(hh, h, h);
                    FMA2(acc[j][0], hh, (unsigned long long)w01.x);
                    FMA2(acc[j][1], hh, (unsigned long long)w01.y);
                    FMA2(acc[j][2], hh, (unsigned long long)w23.x);
                    FMA2(acc[j][3], hh, (unsigned long long)w23.y);
                }
            }
        }
        __syncthreads();
    }
    #pragma unroll
    for (int j = 0; j < 4; j++) {
        int gr = row0 + ty + j * 32;
        if (gr < NN) {
            unsigned s0, s1, s2, s3;
            float lo, hi;
            UNPACKF2(lo, hi, acc[j][0]); PACKH2(s0, lo, hi);
            UNPACKF2(lo, hi, acc[j][1]); PACKH2(s1, lo, hi);
            UNPACKF2(lo, hi, acc[j][2]); PACKH2(s2, lo, hi);
            UNPACKF2(lo, hi, acc[j][3]); PACKH2(s3, lo, hi);
            // group 2tx at byte 32tx; real slot +0, imag slot +8; group 2tx+1 at +16
            char* base = OutB + (size_t)gr * 256 + 32 * tx + ri * 8;
            *(uint2*)(base)      = make_uint2(s0, s1);   // cols 8tx..8tx+3
            *(uint2*)(base + 16) = make_uint2(s2, s3);   // cols 8tx+4..8tx+7
        }
    }
}

// ---------------- CSR build (once per launch; topology shared by 3 layers) ---
__global__ void hist_k(const int* __restrict__ rows) {
    int e = blockIdx.x * 256 + threadIdx.x;
    if (e < TOTE) atomicAdd(&g_cnt[rows[e]], 1);
}

// one-block exclusive scan: 1024 threads x 49-element chunks
__global__ void scan_k() {
    const int CHUNK = 49;                 // 1024*49 = 50176 >= NN+1
    __shared__ int sm[1024];
    int t = threadIdx.x;
    int base = t * CHUNK;
    int sum = 0;
    #pragma unroll
    for (int i = 0; i < CHUNK; i++) {
        int idx = base + i;
        if (idx < NN) sum += g_cnt[idx];
    }
    sm[t] = sum;
    __syncthreads();
    #pragma unroll
    for (int d = 1; d < 1024; d <<= 1) {
        int v = (t >= d) ? sm[t - d] : 0;
        __syncthreads();
        sm[t] += v;
        __syncthreads();
    }
    int run = (t == 0) ? 0 : sm[t - 1];
    #pragma unroll
    for (int i = 0; i < CHUNK; i++) {
        int idx = base + i;
        if (idx < NN) {
            g_off[idx]    = run;
            g_cursor[idx] = run;
            run += g_cnt[idx];
        } else if (idx == NN) {
            g_off[NN] = run;
        }
    }
}

__global__ void scatter_k(const int* __restrict__ rows, const int* __restrict__ cols,
                          const float* __restrict__ vr, const float* __restrict__ vi) {
    int e = blockIdx.x * 256 + threadIdx.x;
    if (e <= NN) g_cnt[e] = 0;            // re-zero for next graph replay
    if (e >= TOTE) return;
    int k = (e >= 2 * EDG) ? 2 : (e >= EDG) ? 1 : 0;
    int r = rows[e];
    int pos = atomicAdd(&g_cursor[r], 1);
    __half2 hv = __floats2half2_rn(vr[e], vi[e]);
    int2 pay;
    pay.x = k * NN + cols[e];
    pay.y = *(int*)&hv;
    g_epay[pos] = pay;
}

// ---------------- SpMM gather: half-warp per edge, high-MLP main loop --------
__global__ void spmm_gather_k(const float* __restrict__ bias) {
    int w    = (blockIdx.x * 256 + threadIdx.x) >> 5;
    int lane = threadIdx.x & 31;
    if (w >= NN) return;
    int half_id = lane >> 4;     // edge subgroup
    int l16     = lane & 15;     // channel group (4 channels)

    float aR0=0.f, aR1=0.f, aR2=0.f, aR3=0.f;
    float aI0=0.f, aI1=0.f, aI2=0.f, aI3=0.f;

    const char* Ab = (const char*)g_A + l16 * 16;
    int beg = g_off[w], end = g_off[w + 1];
    int e = beg;

    for (; e + 8 <= end; e += 8) {
        int b4 = e + half_id * 4;
        int2 p0 = g_epay[b4 + 0];
        int2 p1 = g_epay[b4 + 1];
        int2 p2 = g_epay[b4 + 2];
        int2 p3 = g_epay[b4 + 3];
        uint4 q0 = *(const uint4*)(Ab + (((unsigned)p0.x) << 8));
        uint4 q1 = *(const uint4*)(Ab + (((unsigned)p1.x) << 8));
        uint4 q2 = *(const uint4*)(Ab + (((unsigned)p2.x) << 8));
        uint4 q3 = *(const uint4*)(Ab + (((unsigned)p3.x) << 8));
        {
            float2 vv = __half22float2(*(const __half2*)&p0.y);
            float2 r01 = __half22float2(*(const __half2*)&q0.x);
            float2 r23 = __half22float2(*(const __half2*)&q0.y);
            float2 i01 = __half22float2(*(const __half2*)&q0.z);
            float2 i23 = __half22float2(*(const __half2*)&q0.w);
            float a = vv.x, b = vv.y;
            aR0 = fmaf(a, r01.x, fmaf(-b, i01.x, aR0));
            aI0 = fmaf(b, r01.x, fmaf( a, i01.x, aI0));
            aR1 = fmaf(a, r01.y, fmaf(-b, i01.y, aR1));
            aI1 = fmaf(b, r01.y, fmaf( a, i01.y, aI1));
            aR2 = fmaf(a, r23.x, fmaf(-b, i23.x, aR2));
            aI2 = fmaf(b, r23.x, fmaf( a, i23.x, aI2));
            aR3 = fmaf(a, r23.y, fmaf(-b, i23.y, aR3));
            aI3 = fmaf(b, r23.y, fmaf( a, i23.y, aI3));
        }
        {
            float2 vv = __half22float2(*(const __half2*)&p1.y);
            float2 r01 = __half22float2(*(const __half2*)&q1.x);
            float2 r23 = __half22float2(*(const __half2*)&q1.y);
            float2 i01 = __half22float2(*(const __half2*)&q1.z);
            float2 i23 = __half22float2(*(const __half2*)&q1.w);
            float a = vv.x, b = vv.y;
            aR0 = fmaf(a, r01.x, fmaf(-b, i01.x, aR0));
            aI0 = fmaf(b, r01.x, fmaf( a, i01.x, aI0));
            aR1 = fmaf(a, r01.y, fmaf(-b, i01.y, aR1));
            aI1 = fmaf(b, r01.y, fmaf( a, i01.y, aI1));
            aR2 = fmaf(a, r23.x, fmaf(-b, i23.x, aR2));
            aI2 = fmaf(b, r23.x, fmaf( a, i23.x, aI2));
            aR3 = fmaf(a, r23.y, fmaf(-b, i23.y, aR3));
            aI3 = fmaf(b, r23.y, fmaf( a, i23.y, aI3));
        }
        {
            float2 vv = __half22float2(*(const __half2*)&p2.y);
            float2 r01 = __half22float2(*(const __half2*)&q2.x);
            float2 r23 = __half22float2(*(const __half2*)&q2.y);
            float2 i01 = __half22float2(*(const __half2*)&q2.z);
            float2 i23 = __half22float2(*(const __half2*)&q2.w);
            float a = vv.x, b = vv.y;
            aR0 = fmaf(a, r01.x, fmaf(-b, i01.x, aR0));
            aI0 = fmaf(b, r01.x, fmaf( a, i01.x, aI0));
            aR1 = fmaf(a, r01.y, fmaf(-b, i01.y, aR1));
            aI1 = fmaf(b, r01.y, fmaf( a, i01.y, aI1));
            aR2 = fmaf(a, r23.x, fmaf(-b, i23.x, aR2));
            aI2 = fmaf(b, r23.x, fmaf( a, i23.x, aI2));
            aR3 = fmaf(a, r23.y, fmaf(-b, i23.y, aR3));
            aI3 = fmaf(b, r23.y, fmaf( a, i23.y, aI3));
        }
        {
            float2 vv = __half22float2(*(const __half2*)&p3.y);
            float2 r01 = __half22float2(*(const __half2*)&q3.x);
            float2 r23 = __half22float2(*(const __half2*)&q3.y);
            float2 i01 = __half22float2(*(const __half2*)&q3.z);
            float2 i23 = __half22float2(*(const __half2*)&q3.w);
            float a = vv.x, b = vv.y;
            aR0 = fmaf(a, r01.x, fmaf(-b, i01.x, aR0));
            aI0 = fmaf(b, r01.x, fmaf( a, i01.x, aI0));
            aR1 = fmaf(a, r01.y, fmaf(-b, i01.y, aR1));
            aI1 = fmaf(b, r01.y, fmaf( a, i01.y, aI1));
            aR2 = fmaf(a, r23.x, fmaf(-b, i23.x, aR2));
            aI2 = fmaf(b, r23.x, fmaf( a, i23.x, aI2));
            aR3 = fmaf(a, r23.y, fmaf(-b, i23.y, aR3));
            aI3 = fmaf(b, r23.y, fmaf( a, i23.y, aI3));
        }
    }
    // tail: 2 edges per iteration, guarded
    for (; e < end; e += 2) {
        int ee = e + half_id;
        int ec = min(ee, end - 1);
        int2 p = g_epay[ec];
        float2 vv = __half22float2(*(const __half2*)&p.y);
        float a = (ee < end) ? vv.x : 0.f;
        float b = (ee < end) ? vv.y : 0.f;
        uint4 q = *(const uint4*)(Ab + (((unsigned)p.x) << 8));
        float2 r01 = __half22float2(*(const __half2*)&q.x);
        float2 r23 = __half22float2(*(const __half2*)&q.y);
        float2 i01 = __half22float2(*(const __half2*)&q.z);
        float2 i23 = __half22float2(*(const __half2*)&q.w);
        aR0 = fmaf(a, r01.x, fmaf(-b, i01.x, aR0));
        aI0 = fmaf(b, r01.x, fmaf( a, i01.x, aI0));
        aR1 = fmaf(a, r01.y, fmaf(-b, i01.y, aR1));
        aI1 = fmaf(b, r01.y, fmaf( a, i01.y, aI1));
        aR2 = fmaf(a, r23.x, fmaf(-b, i23.x, aR2));
        aI2 = fmaf(b, r23.x, fmaf( a, i23.x, aI2));
        aR3 = fmaf(a, r23.y, fmaf(-b, i23.y, aR3));
        aI3 = fmaf(b, r23.y, fmaf( a, i23.y, aI3));
    }

    // combine the two half-warps' partials
    aR0 += __shfl_xor_sync(0xffffffffu, aR0, 16);
    aR1 += __shfl_xor_sync(0xffffffffu, aR1, 16);
    aR2 += __shfl_xor_sync(0xffffffffu, aR2, 16);
    aR3 += __shfl_xor_sync(0xffffffffu, aR3, 16);
    aI0 += __shfl_xor_sync(0xffffffffu, aI0, 16);
    aI1 += __shfl_xor_sync(0xffffffffu, aI1, 16);
    aI2 += __shfl_xor_sync(0xffffffffu, aI2, 16);
    aI3 += __shfl_xor_sync(0xffffffffu, aI3, 16);

    if (half_id == 0) {
        float4 bv = *(const float4*)&bias[l16 * 4];
        float r0 = aR0 + bv.x, r1 = aR1 + bv.y, r2 = aR2 + bv.z, r3 = aR3 + bv.w;
        float i0 = aI0 + bv.x, i1 = aI1 + bv.y, i2 = aI2 + bv.z, i3 = aI3 + bv.w;
        float4 hr, hi;
        hr.x = (r0 >= 0.f) ? r0 : 0.f;  hi.x = (r0 >= 0.f) ? i0 : 0.f;
        hr.y = (r1 >= 0.f) ? r1 : 0.f;  hi.y = (r1 >= 0.f) ? i1 : 0.f;
        hr.z = (r2 >= 0.f) ? r2 : 0.f;  hi.z = (r2 >= 0.f) ? i2 : 0.f;
        hr.w = (r3 >= 0.f) ? r3 : 0.f;  hi.w = (r3 >= 0.f) ? i3 : 0.f;
        *(float4*)&g_Hr[w * NF + l16 * 4] = hr;
        *(float4*)&g_Hi[w * NF + l16 * 4] = hi;
    }
}

// ---------------- CBAM channel attention -------------------------------------
__global__ void zero_cmean_k() {
    if (threadIdx.x < CCH) g_cmean[threadIdx.x] = 0.f;
}

__global__ void chan_sum_k() {
    const int NPB = 512;
    int t = threadIdx.x;            // 256
    int c = t & 127;
    int half = t >> 7;
    int n0 = blockIdx.x * NPB;
    int n1 = min(n0 + NPB, NN);
    const float* src = (c < NF) ? g_Hr : g_Hi;
    int cc = c & (NF - 1);
    float s = 0.f;
    for (int n = n0 + half; n < n1; n += 2) s += src[n * NF + cc];
    __shared__ float sm[256];
    sm[t] = s;
    __syncthreads();
    if (t < 128) atomicAdd(&g_cmean[c], sm[t] + sm[t + 128]);
}

__global__ void ca_k(const float* __restrict__ w1, const float* __restrict__ w2) {
    __shared__ float avg[CCH];
    __shared__ float hid[8];
    int t = threadIdx.x;            // 128
    avg[t] = g_cmean[t] * (1.f / (float)NN);
    __syncthreads();
    if (t < 8) {
        float s = 0.f;
        #pragma unroll 4
        for (int c = 0; c < CCH; c++) s += w1[t * CCH + c] * avg[c];
        hid[t] = fmaxf(s, 0.f);
    }
    __syncthreads();
    float o = 0.f;
    #pragma unroll
    for (int r = 0; r < 8; r++) o += w2[t * 8 + r] * hid[r];
    g_ca[t] = 1.f / (1.f + expf(-o));
}

// ---------------- spatial stats (after CA scaling) ---------------------------
__global__ void sstat_k() {
    __shared__ float ca[CCH];
    if (threadIdx.x < CCH) ca[threadIdx.x] = g_ca[threadIdx.x];
    __syncthreads();
    int n = blockIdx.x * blockDim.x + threadIdx.x;
    if (n >= NN) return;
    float sum = 0.f, mx = -1e30f;
    const float4* hr = (const float4*)&g_Hr[n * NF];
    #pragma unroll
    for (int j = 0; j < 16; j++) {
        float4 v = hr[j];
        float a0 = v.x * ca[j*4+0], a1 = v.y * ca[j*4+1];
        float a2 = v.z * ca[j*4+2], a3 = v.w * ca[j*4+3];
        sum += a0 + a1 + a2 + a3;
        mx = fmaxf(mx, fmaxf(fmaxf(a0, a1), fmaxf(a2, a3)));
    }
    const float4* hi = (const float4*)&g_Hi[n * NF];
    #pragma unroll
    for (int j = 0; j < 16; j++) {
        float4 v = hi[j];
        float a0 = v.x * ca[64+j*4+0], a1 = v.y * ca[64+j*4+1];
        float a2 = v.z * ca[64+j*4+2], a3 = v.w * ca[64+j*4+3];
        sum += a0 + a1 + a2 + a3;
        mx = fmaxf(mx, fmaxf(fmaxf(a0, a1), fmaxf(a2, a3)));
    }
    g_smean[n] = sum * (1.f / (float)CCH);
    g_smax[n]  = mx;
}

// ---------------- spatial attention + final conv + log_softmax ---------------
__global__ void final_k(const float* __restrict__ sa_w,
                        const float* __restrict__ conv_w,
                        const float* __restrict__ conv_b,
                        float* __restrict__ out) {
    __shared__ float ca[CCH];
    __shared__ float cw[LABEL * CCH];
    __shared__ float cb[LABEL];
    __shared__ float sw[14];
    int t = threadIdx.x;
    if (t < CCH) ca[t] = g_ca[t];
    for (int idx = t; idx < LABEL * CCH; idx += blockDim.x) cw[idx] = conv_w[idx];
    if (t < LABEL) cb[t] = conv_b[t];
    if (t < 14) sw[t] = sa_w[t];
    __syncthreads();

    int n = blockIdx.x * blockDim.x + t;
    if (n >= NN) return;

    float s = 0.f;
    #pragma unroll
    for (int tap = 0; tap < 7; tap++) {
        int m = n - 3 + tap;
        if (m >= 0 && m < NN) s += sw[tap] * g_smean[m] + sw[7 + tap] * g_smax[m];
    }
    float sa = 1.f / (1.f + expf(-s));

    float acc[LABEL];
    #pragma unroll
    for (int l = 0; l < LABEL; l++) acc[l] = cb[l];

    const float* hr = &g_Hr[n * NF];
    const float* hi = &g_Hi[n * NF];
    #pragma unroll 4
    for (int c = 0; c < NF; c++) {
        float xv = hr[c] * ca[c] * sa;
        #pragma unroll
        for (int l = 0; l < LABEL; l++) acc[l] += cw[l * CCH + c] * xv;
    }
    #pragma unroll 4
    for (int c = 0; c < NF; c++) {
        float xv = hi[c] * ca[NF + c] * sa;
        #pragma unroll
        for (int l = 0; l < LABEL; l++) acc[l] += cw[l * CCH + NF + c] * xv;
    }

    float mx = acc[0];
    #pragma unroll
    for (int l = 1; l < LABEL; l++) mx = fmaxf(mx, acc[l]);
    float se = 0.f;
    #pragma unroll
    for (int l = 0; l < LABEL; l++) se += expf(acc[l] - mx);
    float lse = logf(se) + mx;
    #pragma unroll
    for (int l = 0; l < LABEL; l++) out[l * NN + n] = acc[l] - lse;
}

// ---------------- launch sequence --------------------------------------------
extern "C" void kernel_launch(void* const* d_in, const int* in_sizes, int n_in,
                              void* d_out, int out_size) {
    const float* Xr    = (const float*)d_in[0];
    const float* Xi    = (const float*)d_in[1];
    const int*   rows  = (const int*)  d_in[2];
    const int*   cols  = (const int*)  d_in[3];
    const float* vr    = (const float*)d_in[4];
    const float* vi    = (const float*)d_in[5];
    const float* w0    = (const float*)d_in[6];
    const float* b0    = (const float*)d_in[7];
    const float* w1    = (const float*)d_in[8];
    const float* b1    = (const float*)d_in[9];
    const float* w2    = (const float*)d_in[10];
    const float* b2    = (const float*)d_in[11];
    const float* caw1  = (const float*)d_in[12];
    const float* caw2  = (const float*)d_in[13];
    const float* saw   = (const float*)d_in[14];
    const float* convw = (const float*)d_in[15];
    const float* convb = (const float*)d_in[16];
    float* out = (float*)d_out;

    const dim3 gemm_grid((NN + 127) / 128, 6);
    const int edge_blocks   = (TOTE + 255) / 256;
    const int gather_blocks = (NN * 32 + 255) / 256;
    const int node_blocks   = (NN + 255) / 256;

    // ---- CSR build (reused by all 3 layers) ----
    hist_k<<<edge_blocks, 256>>>(rows);                       // launch 0
    scan_k<<<1, 1024>>>();                                    // launch 1
    scatter_k<<<edge_blocks, 256>>>(rows, cols, vr, vi);      // launch 2

    // ---- layer 0 (FIN=128, inputs from d_in) ----
    gemm_k<INC, false><<<gemm_grid, 256>>>(Xr, Xi, w0);       // launch 3 (profiled)
    spmm_gather_k<<<gather_blocks, 256>>>(b0);

    // ---- layer 1 ----
    gemm_k<NF, true><<<gemm_grid, 256>>>(nullptr, nullptr, w1);
    spmm_gather_k<<<gather_blocks, 256>>>(b1);

    // ---- layer 2 ----
    gemm_k<NF, true><<<gemm_grid, 256>>>(nullptr, nullptr, w2);
    spmm_gather_k<<<gather_blocks, 256>>>(b2);

    // ---- CBAM + head ----
    zero_cmean_k<<<1, 128>>>();
    chan_sum_k<<<(NN + 511) / 512, 256>>>();
    ca_k<<<1, 128>>>(caw1, caw2);
    sstat_k<<<node_blocks, 256>>>();
    final_k<<<node_blocks, 256>>>(saw, convw, convb, out);
}

// round 12
// speedup vs baseline: 2.1170x; 1.1806x over previous
#include <cuda_runtime.h>
#include <cuda_bf16.h>
#include <cuda_fp16.h>
#include <math.h>

#define NN    50000
#define EDG   800000
#define K1    3
#define INC   128
#define NF    64
#define CCH   128   // 2*NF
#define LABEL 10
#define TOTE  (K1*EDG)

// packed fp32x2 FMA (Blackwell FFMA2; ptxas never emits it from C++)
#define FMA2(d, a, b) \
    asm("fma.rn.f32x2 %0, %1, %2, %0;" : "+l"(d) : "l"(a), "l"(b))
#define PACKF2(d, lo, hi) \
    asm("mov.b64 %0, {%1, %2};" : "=l"(d) : "f"(lo), "f"(hi))
#define UNPACKF2(lo, hi, s) \
    asm("mov.b64 {%0, %1}, %2;" : "=f"(lo), "=f"(hi) : "l"(s))
#define PACKH2(d, lo, hi) \
    asm("cvt.rn.f16x2.f32 %0, %1, %2;" : "=r"(d) : "f"(hi), "f"(lo))

// ---------------- scratch (device globals; no allocs allowed) ----------------
// A layout per (k,node): 16 groups of 16B; group g = (r_{4g..4g+3}, i_{4g..4g+3}) fp16
__device__ __half g_A[(size_t)K1 * NN * CCH];
__device__ float g_Hr[NN * NF];               // hidden (real, post-activation)
__device__ float g_Hi[NN * NF];
__device__ int   g_cnt[NN + 1];               // zero-init at load; re-zeroed by scatter_k
__device__ int   g_off[NN + 1];
__device__ int   g_cursor[NN];
__device__ int2  g_epay[TOTE];                // (k*NN+c, half2(vr,vi))
__device__ float g_cmean[CCH];
__device__ float g_ca[CCH];
__device__ float g_smean[NN];
__device__ float g_smax[NN];

// ---------------- GEMM (FFMA2, fp32 math): interleaved fp16 A output ---------
// grid.x tiles 128 rows; grid.y = 6 (k*2 + ri). block = 256, >=4 blocks/SM.
// Hs stride 36 floats: 16B-aligned rows, conflict-free float4 row reads.
// Ws stores 16B unit u at phys ((u&1)<<3)|(u>>1): both W reads are 1-phase.
template<int FIN, bool FROMG>
__global__ void __launch_bounds__(256, 4)
gemm_k(const float* __restrict__ HrIn, const float* __restrict__ HiIn,
       const float* __restrict__ Wall) {
    const int z  = blockIdx.y;
    const int k  = z >> 1, ri = z & 1;
    const float* H;
    if (FROMG) H = ri ? g_Hi : g_Hr;
    else       H = ri ? HiIn : HrIn;
    const float* W = Wall + k * FIN * NF;
    char* OutB = (char*)g_A + (size_t)k * NN * 256;   // 256B per node row

    const int row0 = blockIdx.x * 128;
    const int tid  = threadIdx.x;
    const int tx   = tid & 7;       // col group: cols tx*8 .. tx*8+7
    const int ty   = tid >> 3;      // 0..31 ; rows ty + j*32

    __shared__ float Hs[128 * 36];  // stride 36
    __shared__ float Ws[32 * 64];   // unit-permuted rows

    unsigned long long acc[4][4];   // [row j][col pair]
    #pragma unroll
    for (int j = 0; j < 4; j++)
        #pragma unroll
        for (int p = 0; p < 4; p++) acc[j][p] = 0ull;

    for (int kc = 0; kc < FIN; kc += 32) {
        // H tile [128 x 32] via float4 (8 f4 per row)
        #pragma unroll
        for (int t = 0; t < 4; t++) {
            int idx = tid + t * 256;          // 0..1023
            int r   = idx >> 3, c4 = idx & 7;
            int gr  = row0 + r;
            float4 v = (gr < NN) ? *(const float4*)&H[(size_t)gr * FIN + kc + c4 * 4]
                                 : make_float4(0.f, 0.f, 0.f, 0.f);
            *(float4*)&Hs[r * 36 + c4 * 4] = v;
        }
        // W tile [32 x 64] via float4, unit-permuted: logical unit c4 -> phys
        #pragma unroll
        for (int t = 0; t < 2; t++) {
            int idx = tid + t * 256;          // 0..511
            int i   = idx >> 4, c4 = idx & 15;
            int pc4 = ((c4 & 1) << 3) | (c4 >> 1);
            *(float4*)&Ws[i * 64 + pc4 * 4] = *(const float4*)&W[(kc + i) * NF + c4 * 4];
        }
        __syncthreads();
        #pragma unroll
        for (int i4 = 0; i4 < 8; i4++) {
            float4 h4[4];
            #pragma unroll
            for (int j = 0; j < 4; j++)
                h4[j] = *(const float4*)&Hs[(ty + j * 32) * 36 + i4 * 4];
            #pragma unroll
            for (int ii = 0; ii < 4; ii++) {
                const float* wrow = &Ws[(i4 * 4 + ii) * 64];
                longlong2 w01 = *(const longlong2*)(wrow + tx * 4);        // phys tx
                longlong2 w23 = *(const longlong2*)(wrow + 32 + tx * 4);   // phys 8+tx
                #pragma unroll
                for (int j = 0; j < 4; j++) {
                    float h = (ii == 0) ? h4[j].x : (ii == 1) ? h4[j].y
                            : (ii == 2) ? h4[j].z : h4[j].w;
                    unsigned long long hh;
                    PACKF2(hh, h, h);
                    FMA2(acc[j][0], hh, (unsigned long long)w01.x);
                    FMA2(acc[j][1], hh, (unsigned long long)w01.y);
                    FMA2(acc[j][2], hh, (unsigned long long)w23.x);
                    FMA2(acc[j][3], hh, (unsigned long long)w23.y);
                }
            }
        }
        __syncthreads();
    }
    #pragma unroll
    for (int j = 0; j < 4; j++) {
        int gr = row0 + ty + j * 32;
        if (gr < NN) {
            unsigned s0, s1, s2, s3;
            float lo, hi;
            UNPACKF2(lo, hi, acc[j][0]); PACKH2(s0, lo, hi);
            UNPACKF2(lo, hi, acc[j][1]); PACKH2(s1, lo, hi);
            UNPACKF2(lo, hi, acc[j][2]); PACKH2(s2, lo, hi);
            UNPACKF2(lo, hi, acc[j][3]); PACKH2(s3, lo, hi);
            // group 2tx at byte 32tx; real slot +0, imag slot +8; group 2tx+1 at +16
            char* base = OutB + (size_t)gr * 256 + 32 * tx + ri * 8;
            *(uint2*)(base)      = make_uint2(s0, s1);   // cols 8tx..8tx+3
            *(uint2*)(base + 16) = make_uint2(s2, s3);   // cols 8tx+4..8tx+7
        }
    }
}

// ---------------- CSR build (once per launch; topology shared by 3 layers) ---
__global__ void hist_k(const int* __restrict__ rows) {
    int e = blockIdx.x * 256 + threadIdx.x;
    if (e < TOTE) atomicAdd(&g_cnt[rows[e]], 1);
}

// one-block exclusive scan: 1024 threads x 49-element chunks
__global__ void scan_k() {
    const int CHUNK = 49;                 // 1024*49 = 50176 >= NN+1
    __shared__ int sm[1024];
    int t = threadIdx.x;
    int base = t * CHUNK;
    int sum = 0;
    #pragma unroll
    for (int i = 0; i < CHUNK; i++) {
        int idx = base + i;
        if (idx < NN) sum += g_cnt[idx];
    }
    sm[t] = sum;
    __syncthreads();
    #pragma unroll
    for (int d = 1; d < 1024; d <<= 1) {
        int v = (t >= d) ? sm[t - d] : 0;
        __syncthreads();
        sm[t] += v;
        __syncthreads();
    }
    int run = (t == 0) ? 0 : sm[t - 1];
    #pragma unroll
    for (int i = 0; i < CHUNK; i++) {
        int idx = base + i;
        if (idx < NN) {
            g_off[idx]    = run;
            g_cursor[idx] = run;
            run += g_cnt[idx];
        } else if (idx == NN) {
            g_off[NN] = run;
        }
    }
}

__global__ void scatter_k(const int* __restrict__ rows, const int* __restrict__ cols,
                          const float* __restrict__ vr, const float* __restrict__ vi) {
    int e = blockIdx.x * 256 + threadIdx.x;
    if (e <= NN) g_cnt[e] = 0;            // re-zero for next graph replay
    if (e >= TOTE) return;
    int k = (e >= 2 * EDG) ? 2 : (e >= EDG) ? 1 : 0;
    int r = rows[e];
    int pos = atomicAdd(&g_cursor[r], 1);
    __half2 hv = __floats2half2_rn(vr[e], vi[e]);
    int2 pay;
    pay.x = k * NN + cols[e];
    pay.y = *(int*)&hv;
    g_epay[pos] = pay;
}

// ---------------- SpMM gather: half-warp per edge, high-MLP main loop --------
__global__ void spmm_gather_k(const float* __restrict__ bias) {
    int w    = (blockIdx.x * 256 + threadIdx.x) >> 5;
    int lane = threadIdx.x & 31;
    if (w >= NN) return;
    int half_id = lane >> 4;     // edge subgroup
    int l16     = lane & 15;     // channel group (4 channels)

    float aR0=0.f, aR1=0.f, aR2=0.f, aR3=0.f;
    float aI0=0.f, aI1=0.f, aI2=0.f, aI3=0.f;

    const char* Ab = (const char*)g_A + l16 * 16;
    int beg = g_off[w], end = g_off[w + 1];
    int e = beg;

    for (; e + 8 <= end; e += 8) {
        int b4 = e + half_id * 4;
        int2 p0 = g_epay[b4 + 0];
        int2 p1 = g_epay[b4 + 1];
        int2 p2 = g_epay[b4 + 2];
        int2 p3 = g_epay[b4 + 3];
        uint4 q0 = *(const uint4*)(Ab + (((unsigned)p0.x) << 8));
        uint4 q1 = *(const uint4*)(Ab + (((unsigned)p1.x) << 8));
        uint4 q2 = *(const uint4*)(Ab + (((unsigned)p2.x) << 8));
        uint4 q3 = *(const uint4*)(Ab + (((unsigned)p3.x) << 8));
        {
            float2 vv = __half22float2(*(const __half2*)&p0.y);
            float2 r01 = __half22float2(*(const __half2*)&q0.x);
            float2 r23 = __half22float2(*(const __half2*)&q0.y);
            float2 i01 = __half22float2(*(const __half2*)&q0.z);
            float2 i23 = __half22float2(*(const __half2*)&q0.w);
            float a = vv.x, b = vv.y;
            aR0 = fmaf(a, r01.x, fmaf(-b, i01.x, aR0));
            aI0 = fmaf(b, r01.x, fmaf( a, i01.x, aI0));
            aR1 = fmaf(a, r01.y, fmaf(-b, i01.y, aR1));
            aI1 = fmaf(b, r01.y, fmaf( a, i01.y, aI1));
            aR2 = fmaf(a, r23.x, fmaf(-b, i23.x, aR2));
            aI2 = fmaf(b, r23.x, fmaf( a, i23.x, aI2));
            aR3 = fmaf(a, r23.y, fmaf(-b, i23.y, aR3));
            aI3 = fmaf(b, r23.y, fmaf( a, i23.y, aI3));
        }
        {
            float2 vv = __half22float2(*(const __half2*)&p1.y);
            float2 r01 = __half22float2(*(const __half2*)&q1.x);
            float2 r23 = __half22float2(*(const __half2*)&q1.y);
            float2 i01 = __half22float2(*(const __half2*)&q1.z);
            float2 i23 = __half22float2(*(const __half2*)&q1.w);
            float a = vv.x, b = vv.y;
            aR0 = fmaf(a, r01.x, fmaf(-b, i01.x, aR0));
            aI0 = fmaf(b, r01.x, fmaf( a, i01.x, aI0));
            aR1 = fmaf(a, r01.y, fmaf(-b, i01.y, aR1));
            aI1 = fmaf(b, r01.y, fmaf( a, i01.y, aI1));
            aR2 = fmaf(a, r23.x, fmaf(-b, i23.x, aR2));
            aI2 = fmaf(b, r23.x, fmaf( a, i23.x, aI2));
            aR3 = fmaf(a, r23.y, fmaf(-b, i23.y, aR3));
            aI3 = fmaf(b, r23.y, fmaf( a, i23.y, aI3));
        }
        {
            float2 vv = __half22float2(*(const __half2*)&p2.y);
            float2 r01 = __half22float2(*(const __half2*)&q2.x);
            float2 r23 = __half22float2(*(const __half2*)&q2.y);
            float2 i01 = __half22float2(*(const __half2*)&q2.z);
            float2 i23 = __half22float2(*(const __half2*)&q2.w);
            float a = vv.x, b = vv.y;
            aR0 = fmaf(a, r01.x, fmaf(-b, i01.x, aR0));
            aI0 = fmaf(b, r01.x, fmaf( a, i01.x, aI0));
            aR1 = fmaf(a, r01.y, fmaf(-b, i01.y, aR1));
            aI1 = fmaf(b, r01.y, fmaf( a, i01.y, aI1));
            aR2 = fmaf(a, r23.x, fmaf(-b, i23.x, aR2));
            aI2 = fmaf(b, r23.x, fmaf( a, i23.x, aI2));
            aR3 = fmaf(a, r23.y, fmaf(-b, i23.y, aR3));
            aI3 = fmaf(b, r23.y, fmaf( a, i23.y, aI3));
        }
        {
            float2 vv = __half22float2(*(const __half2*)&p3.y);
            float2 r01 = __half22float2(*(const __half2*)&q3.x);
            float2 r23 = __half22float2(*(const __half2*)&q3.y);
            float2 i01 = __half22float2(*(const __half2*)&q3.z);
            float2 i23 = __half22float2(*(const __half2*)&q3.w);
            float a = vv.x, b = vv.y;
            aR0 = fmaf(a, r01.x, fmaf(-b, i01.x, aR0));
            aI0 = fmaf(b, r01.x, fmaf( a, i01.x, aI0));
            aR1 = fmaf(a, r01.y, fmaf(-b, i01.y, aR1));
            aI1 = fmaf(b, r01.y, fmaf( a, i01.y, aI1));
            aR2 = fmaf(a, r23.x, fmaf(-b, i23.x, aR2));
            aI2 = fmaf(b, r23.x, fmaf( a, i23.x, aI2));
            aR3 = fmaf(a, r23.y, fmaf(-b, i23.y, aR3));
            aI3 = fmaf(b, r23.y, fmaf( a, i23.y, aI3));
        }
    }
    // tail: 2 edges per iteration, guarded
    for (; e < end; e += 2) {
        int ee = e + half_id;
        int ec = min(ee, end - 1);
        int2 p = g_epay[ec];
        float2 vv = __half22float2(*(const __half2*)&p.y);
        float a = (ee < end) ? vv.x : 0.f;
        float b = (ee < end) ? vv.y : 0.f;
        uint4 q = *(const uint4*)(Ab + (((unsigned)p.x) << 8));
        float2 r01 = __half22float2(*(const __half2*)&q.x);
        float2 r23 = __half22float2(*(const __half2*)&q.y);
        float2 i01 = __half22float2(*(const __half2*)&q.z);
        float2 i23 = __half22float2(*(const __half2*)&q.w);
        aR0 = fmaf(a, r01.x, fmaf(-b, i01.x, aR0));
        aI0 = fmaf(b, r01.x, fmaf( a, i01.x, aI0));
        aR1 = fmaf(a, r01.y, fmaf(-b, i01.y, aR1));
        aI1 = fmaf(b, r01.y, fmaf( a, i01.y, aI1));
        aR2 = fmaf(a, r23.x, fmaf(-b, i23.x, aR2));
        aI2 = fmaf(b, r23.x, fmaf( a, i23.x, aI2));
        aR3 = fmaf(a, r23.y, fmaf(-b, i23.y, aR3));
        aI3 = fmaf(b, r23.y, fmaf( a, i23.y, aI3));
    }

    // combine the two half-warps' partials
    aR0 += __shfl_xor_sync(0xffffffffu, aR0, 16);
    aR1 += __shfl_xor_sync(0xffffffffu, aR1, 16);
    aR2 += __shfl_xor_sync(0xffffffffu, aR2, 16);
    aR3 += __shfl_xor_sync(0xffffffffu, aR3, 16);
    aI0 += __shfl_xor_sync(0xffffffffu, aI0, 16);
    aI1 += __shfl_xor_sync(0xffffffffu, aI1, 16);
    aI2 += __shfl_xor_sync(0xffffffffu, aI2, 16);
    aI3 += __shfl_xor_sync(0xffffffffu, aI3, 16);

    if (half_id == 0) {
        float4 bv = *(const float4*)&bias[l16 * 4];
        float r0 = aR0 + bv.x, r1 = aR1 + bv.y, r2 = aR2 + bv.z, r3 = aR3 + bv.w;
        float i0 = aI0 + bv.x, i1 = aI1 + bv.y, i2 = aI2 + bv.z, i3 = aI3 + bv.w;
        float4 hr, hi;
        hr.x = (r0 >= 0.f) ? r0 : 0.f;  hi.x = (r0 >= 0.f) ? i0 : 0.f;
        hr.y = (r1 >= 0.f) ? r1 : 0.f;  hi.y = (r1 >= 0.f) ? i1 : 0.f;
        hr.z = (r2 >= 0.f) ? r2 : 0.f;  hi.z = (r2 >= 0.f) ? i2 : 0.f;
        hr.w = (r3 >= 0.f) ? r3 : 0.f;  hi.w = (r3 >= 0.f) ? i3 : 0.f;
        *(float4*)&g_Hr[w * NF + l16 * 4] = hr;
        *(float4*)&g_Hi[w * NF + l16 * 4] = hi;
    }
}

// ---------------- CBAM channel attention -------------------------------------
__global__ void zero_cmean_k() {
    if (threadIdx.x < CCH) g_cmean[threadIdx.x] = 0.f;
}

__global__ void chan_sum_k() {
    const int NPB = 512;
    int t = threadIdx.x;            // 256
    int c = t & 127;
    int half = t >> 7;
    int n0 = blockIdx.x * NPB;
    int n1 = min(n0 + NPB, NN);
    const float* src = (c < NF) ? g_Hr : g_Hi;
    int cc = c & (NF - 1);
    float s = 0.f;
    for (int n = n0 + half; n < n1; n += 2) s += src[n * NF + cc];
    __shared__ float sm[256];
    sm[t] = s;
    __syncthreads();
    if (t < 128) atomicAdd(&g_cmean[c], sm[t] + sm[t + 128]);
}

__global__ void ca_k(const float* __restrict__ w1, const float* __restrict__ w2) {
    __shared__ float avg[CCH];
    __shared__ float hid[8];
    int t = threadIdx.x;            // 128
    avg[t] = g_cmean[t] * (1.f / (float)NN);
    __syncthreads();
    if (t < 8) {
        float s = 0.f;
        #pragma unroll 4
        for (int c = 0; c < CCH; c++) s += w1[t * CCH + c] * avg[c];
        hid[t] = fmaxf(s, 0.f);
    }
    __syncthreads();
    float o = 0.f;
    #pragma unroll
    for (int r = 0; r < 8; r++) o += w2[t * 8 + r] * hid[r];
    g_ca[t] = 1.f / (1.f + expf(-o));
}

// ---------------- spatial stats (after CA scaling) ---------------------------
__global__ void sstat_k() {
    __shared__ float ca[CCH];
    if (threadIdx.x < CCH) ca[threadIdx.x] = g_ca[threadIdx.x];
    __syncthreads();
    int n = blockIdx.x * blockDim.x + threadIdx.x;
    if (n >= NN) return;
    float sum = 0.f, mx = -1e30f;
    const float4* hr = (const float4*)&g_Hr[n * NF];
    #pragma unroll
    for (int j = 0; j < 16; j++) {
        float4 v = hr[j];
        float a0 = v.x * ca[j*4+0], a1 = v.y * ca[j*4+1];
        float a2 = v.z * ca[j*4+2], a3 = v.w * ca[j*4+3];
        sum += a0 + a1 + a2 + a3;
        mx = fmaxf(mx, fmaxf(fmaxf(a0, a1), fmaxf(a2, a3)));
    }
    const float4* hi = (const float4*)&g_Hi[n * NF];
    #pragma unroll
    for (int j = 0; j < 16; j++) {
        float4 v = hi[j];
        float a0 = v.x * ca[64+j*4+0], a1 = v.y * ca[64+j*4+1];
        float a2 = v.z * ca[64+j*4+2], a3 = v.w * ca[64+j*4+3];
        sum += a0 + a1 + a2 + a3;
        mx = fmaxf(mx, fmaxf(fmaxf(a0, a1), fmaxf(a2, a3)));
    }
    g_smean[n] = sum * (1.f / (float)CCH);
    g_smax[n]  = mx;
}

// ---------------- spatial attention + final conv + log_softmax ---------------
__global__ void final_k(const float* __restrict__ sa_w,
                        const float* __restrict__ conv_w,
                        const float* __restrict__ conv_b,
                        float* __restrict__ out) {
    __shared__ float ca[CCH];
    __shared__ float cw[LABEL * CCH];
    __shared__ float cb[LABEL];
    __shared__ float sw[14];
    int t = threadIdx.x;
    if (t < CCH) ca[t] = g_ca[t];
    for (int idx = t; idx < LABEL * CCH; idx += blockDim.x) cw[idx] = conv_w[idx];
    if (t < LABEL) cb[t] = conv_b[t];
    if (t < 14) sw[t] = sa_w[t];
    __syncthreads();

    int n = blockIdx.x * blockDim.x + t;
    if (n >= NN) return;

    float s = 0.f;
    #pragma unroll
    for (int tap = 0; tap < 7; tap++) {
        int m = n - 3 + tap;
        if (m >= 0 && m < NN) s += sw[tap] * g_smean[m] + sw[7 + tap] * g_smax[m];
    }
    float sa = 1.f / (1.f + expf(-s));

    float acc[LABEL];
    #pragma unroll
    for (int l = 0; l < LABEL; l++) acc[l] = cb[l];

    const float* hr = &g_Hr[n * NF];
    const float* hi = &g_Hi[n * NF];
    #pragma unroll 4
    for (int c = 0; c < NF; c++) {
        float xv = hr[c] * ca[c] * sa;
        #pragma unroll
        for (int l = 0; l < LABEL; l++) acc[l] += cw[l * CCH + c] * xv;
    }
    #pragma unroll 4
    for (int c = 0; c < NF; c++) {
        float xv = hi[c] * ca[NF + c] * sa;
        #pragma unroll
        for (int l = 0; l < LABEL; l++) acc[l] += cw[l * CCH + NF + c] * xv;
    }

    float mx = acc[0];
    #pragma unroll
    for (int l = 1; l < LABEL; l++) mx = fmaxf(mx, acc[l]);
    float se = 0.f;
    #pragma unroll
    for (int l = 0; l < LABEL; l++) se += expf(acc[l] - mx);
    float lse = logf(se) + mx;
    #pragma unroll
    for (int l = 0; l < LABEL; l++) out[l * NN + n] = acc[l] - lse;
}

// ---------------- launch sequence --------------------------------------------
extern "C" void kernel_launch(void* const* d_in, const int* in_sizes, int n_in,
                              void* d_out, int out_size) {
    const float* Xr    = (const float*)d_in[0];
    const float* Xi    = (const float*)d_in[1];
    const int*   rows  = (const int*)  d_in[2];
    const int*   cols  = (const int*)  d_in[3];
    const float* vr    = (const float*)d_in[4];
    const float* vi    = (const float*)d_in[5];
    const float* w0    = (const float*)d_in[6];
    const float* b0    = (const float*)d_in[7];
    const float* w1    = (const float*)d_in[8];
    const float* b1    = (const float*)d_in[9];
    const float* w2    = (const float*)d_in[10];
    const float* b2    = (const float*)d_in[11];
    const float* caw1  = (const float*)d_in[12];
    const float* caw2  = (const float*)d_in[13];
    const float* saw   = (const float*)d_in[14];
    const float* convw = (const float*)d_in[15];
    const float* convb = (const float*)d_in[16];
    float* out = (float*)d_out;

    const dim3 gemm_grid((NN + 127) / 128, 6);
    const int edge_blocks   = (TOTE + 255) / 256;
    const int gather_blocks = (NN * 32 + 255) / 256;
    const int node_blocks   = (NN + 255) / 256;

    // ---- CSR build (reused by all 3 layers) ----
    hist_k<<<edge_blocks, 256>>>(rows);                       // launch 0
    scan_k<<<1, 1024>>>();                                    // launch 1
    scatter_k<<<edge_blocks, 256>>>(rows, cols, vr, vi);      // launch 2

    // ---- layer 0 (FIN=128, inputs from d_in) ----
    gemm_k<INC, false><<<gemm_grid, 256>>>(Xr, Xi, w0);       // launch 3 (profiled)
    spmm_gather_k<<<gather_blocks, 256>>>(b0);

    // ---- layer 1 ----
    gemm_k<NF, true><<<gemm_grid, 256>>>(nullptr, nullptr, w1);
    spmm_gather_k<<<gather_blocks, 256>>>(b1);

    // ---- layer 2 ----
    gemm_k<NF, true><<<gemm_grid, 256>>>(nullptr, nullptr, w2);
    spmm_gather_k<<<gather_blocks, 256>>>(b2);

    // ---- CBAM + head ----
    zero_cmean_k<<<1, 128>>>();
    chan_sum_k<<<(NN + 511) / 512, 256>>>();
    ca_k<<<1, 128>>>(caw1, caw2);
    sstat_k<<<node_blocks, 256>>>();
    final_k<<<node_blocks, 256>>>(saw, convw, convb, out);
}

// round 14
// speedup vs baseline: 2.4349x; 1.1502x over previous
#include <cuda_runtime.h>
#include <cuda_bf16.h>
#include <cuda_fp16.h>
#include <math.h>

#define NN    50000
#define EDG   800000
#define K1    3
#define INC   128
#define NF    64
#define CCH   128   // 2*NF
#define LABEL 10
#define TOTE  (K1*EDG)

#define PACKH2(d, lo, hi) \
    asm("cvt.rn.f16x2.f32 %0, %1, %2;" : "=r"(d) : "f"(hi), "f"(lo))
#define PACKB2(d, lo, hi) \
    asm("cvt.rn.bf16x2.f32 %0, %1, %2;" : "=r"(d) : "f"(hi), "f"(lo))

// ---------------- scratch (device globals; no allocs allowed) ----------------
// A layout per (k,node): 16 groups of 16B; group g = (r_{4g..4g+3}, i_{4g..4g+3}) fp16
__device__ __half g_A[(size_t)K1 * NN * CCH];
__device__ float g_Hr[NN * NF];               // hidden (real, post-activation)
__device__ float g_Hi[NN * NF];
__device__ int   g_cnt[NN + 1];               // zero-init at load; re-zeroed by scatter_k
__device__ int   g_off[NN + 1];
__device__ int   g_cursor[NN];
__device__ int2  g_epay[TOTE];                // (k*NN+c, half2(vr,vi))
__device__ float g_cmean[CCH];
__device__ float g_ca[CCH];
__device__ float g_smean[NN];
__device__ float g_smax[NN];

// ---------------- tensor-core helpers (bf16) ----------------------------------
__device__ __forceinline__ void ldsm_x4(unsigned* r, unsigned addr) {
    asm volatile("ldmatrix.sync.aligned.m8n8.x4.shared.b16 {%0,%1,%2,%3}, [%4];"
                 : "=r"(r[0]), "=r"(r[1]), "=r"(r[2]), "=r"(r[3]) : "r"(addr));
}
__device__ __forceinline__ void ldsm_x4_t(unsigned* r, unsigned addr) {
    asm volatile("ldmatrix.sync.aligned.m8n8.x4.trans.shared.b16 {%0,%1,%2,%3}, [%4];"
                 : "=r"(r[0]), "=r"(r[1]), "=r"(r[2]), "=r"(r[3]) : "r"(addr));
}
__device__ __forceinline__ void mma_bf16(float* c, const unsigned* a, const unsigned* b) {
    asm volatile(
        "mma.sync.aligned.m16n8k16.row.col.f32.bf16.bf16.f32 "
        "{%0,%1,%2,%3}, {%4,%5,%6,%7}, {%8,%9}, {%0,%1,%2,%3};"
        : "+f"(c[0]), "+f"(c[1]), "+f"(c[2]), "+f"(c[3])
        : "r"(a[0]), "r"(a[1]), "r"(a[2]), "r"(a[3]), "r"(b[0]), "r"(b[1]));
}

// split fp32 -> (hi, lo) bf16 pairs, packed 2-wide.
// bf16 covers fp32 exponent range: residuals are never subnormal.
__device__ __forceinline__ void split2b(float x, float y, unsigned& h, unsigned& l) {
    PACKB2(h, x, y);
    __nv_bfloat162 hh = *(__nv_bfloat162*)&h;
    float2 f = __bfloat1622float2(hh);
    PACKB2(l, x - f.x, y - f.y);
}

// ---------------- GEMM (tensor, split-bf16): A[k,ri] = H(ri) @ W[k] ----------
// block = 128 (4 warps), M-tile = 64 rows, N = 64, K chunked at 64.
// grid = (ceil(NN/64), 6). fp32-grade precision via Hh*Wh + Hh*Wl + Hl*Wh.
template<int FIN, bool FROMG>
__global__ void __launch_bounds__(128, 4)
gemm_t(const float* __restrict__ HrIn, const float* __restrict__ HiIn,
       const float* __restrict__ Wall) {
    constexpr int S = 72;              // tile stride in 16-bit units (64 + 8 pad)
    __shared__ __nv_bfloat16 HsH[64 * S], HsL[64 * S];
    __shared__ __nv_bfloat16 WsH[64 * S], WsL[64 * S];

    const int z  = blockIdx.y;
    const int k  = z >> 1, ri = z & 1;
    const float* H;
    if (FROMG) H = ri ? g_Hi : g_Hr;
    else       H = ri ? HiIn : HrIn;
    const float* W = Wall + k * FIN * NF;
    char* OutB = (char*)g_A + (size_t)k * NN * 256;

    const int row0 = blockIdx.x * 64;
    const int tid  = threadIdx.x;
    const int wid  = tid >> 5;
    const int l    = tid & 31;
    const int m0   = wid * 16;

    float acc[8][4];
    #pragma unroll
    for (int t = 0; t < 8; t++)
        #pragma unroll
        for (int j = 0; j < 4; j++) acc[t][j] = 0.f;

    unsigned hbH = (unsigned)__cvta_generic_to_shared(HsH);
    unsigned hbL = (unsigned)__cvta_generic_to_shared(HsL);
    unsigned wbH = (unsigned)__cvta_generic_to_shared(WsH);
    unsigned wbL = (unsigned)__cvta_generic_to_shared(WsL);

    #pragma unroll
    for (int kc = 0; kc < FIN; kc += 64) {
        if (kc) __syncthreads();
        // load H tile [64 x 64] fp32 -> hi/lo bf16
        for (int f = tid; f < 64 * 16; f += 128) {
            int row = f >> 4;
            int c4  = f & 15;
            int gr  = row0 + row;
            float4 v = (gr < NN) ? *(const float4*)&H[(size_t)gr * FIN + kc + c4 * 4]
                                 : make_float4(0.f, 0.f, 0.f, 0.f);
            unsigned h01, l01, h23, l23;
            split2b(v.x, v.y, h01, l01);
            split2b(v.z, v.w, h23, l23);
            *(uint2*)&HsH[row * S + c4 * 4] = make_uint2(h01, h23);
            *(uint2*)&HsL[row * S + c4 * 4] = make_uint2(l01, l23);
        }
        // load W tile [64 x 64] fp32 -> hi/lo bf16
        for (int f = tid; f < 64 * 16; f += 128) {
            int row = f >> 4;
            int c4  = f & 15;
            float4 v = *(const float4*)&W[(kc + row) * NF + c4 * 4];
            unsigned h01, l01, h23, l23;
            split2b(v.x, v.y, h01, l01);
            split2b(v.z, v.w, h23, l23);
            *(uint2*)&WsH[row * S + c4 * 4] = make_uint2(h01, h23);
            *(uint2*)&WsL[row * S + c4 * 4] = make_uint2(l01, l23);
        }
        __syncthreads();

        #pragma unroll
        for (int kk = 0; kk < 64; kk += 16) {
            unsigned aoff = ((m0 + (l & 15)) * S + kk + (l >> 4) * 8) * 2;
            unsigned aH[4], aL[4];
            ldsm_x4(aH, hbH + aoff);
            ldsm_x4(aL, hbL + aoff);
            #pragma unroll
            for (int t = 0; t < 4; t++) {     // each covers 16 output cols
                unsigned boff =
                    ((kk + (l & 7) + ((l >> 3) & 1) * 8) * S + t * 16 + (l >> 4) * 8) * 2;
                unsigned bH[4], bL[4];
                ldsm_x4_t(bH, wbH + boff);
                ldsm_x4_t(bL, wbL + boff);
                mma_bf16(acc[2 * t],     aH, bH);
                mma_bf16(acc[2 * t],     aH, bL);
                mma_bf16(acc[2 * t],     aL, bH);
                mma_bf16(acc[2 * t + 1], aH, bH + 2);
                mma_bf16(acc[2 * t + 1], aH, bL + 2);
                mma_bf16(acc[2 * t + 1], aL, bH + 2);
            }
        }
    }

    // epilogue: c-frag lane l -> rows (l>>2, l>>2+8), cols (2q, 2q+1), q = l&3
    // A-layout contract (matches gather): channel c at byte 16*(c>>2) + ri*8 + (c&3)*2
    const int q   = l & 3;
    const int gr0 = row0 + m0 + (l >> 2);
    const int gr1 = gr0 + 8;
    #pragma unroll
    for (int t = 0; t < 8; t++) {
        unsigned p01, p23;
        PACKH2(p01, acc[t][0], acc[t][1]);
        PACKH2(p23, acc[t][2], acc[t][3]);
        int col = t * 8 + q * 2;
        int off = 16 * (col >> 2) + ri * 8 + (col & 3) * 2;   // FIXED: was 32*
        if (gr0 < NN) *(unsigned*)(OutB + (size_t)gr0 * 256 + off) = p01;
        if (gr1 < NN) *(unsigned*)(OutB + (size_t)gr1 * 256 + off) = p23;
    }
}

// ---------------- CSR build (once per launch; topology shared by 3 layers) ---
__global__ void hist_k(const int* __restrict__ rows) {
    int e = blockIdx.x * 256 + threadIdx.x;
    if (e < TOTE) atomicAdd(&g_cnt[rows[e]], 1);
}

// one-block exclusive scan: 1024 threads x 49-element chunks
__global__ void scan_k() {
    const int CHUNK = 49;                 // 1024*49 = 50176 >= NN+1
    __shared__ int sm[1024];
    int t = threadIdx.x;
    int base = t * CHUNK;
    int sum = 0;
    #pragma unroll
    for (int i = 0; i < CHUNK; i++) {
        int idx = base + i;
        if (idx < NN) sum += g_cnt[idx];
    }
    sm[t] = sum;
    __syncthreads();
    #pragma unroll
    for (int d = 1; d < 1024; d <<= 1) {
        int v = (t >= d) ? sm[t - d] : 0;
        __syncthreads();
        sm[t] += v;
        __syncthreads();
    }
    int run = (t == 0) ? 0 : sm[t - 1];
    #pragma unroll
    for (int i = 0; i < CHUNK; i++) {
        int idx = base + i;
        if (idx < NN) {
            g_off[idx]    = run;
            g_cursor[idx] = run;
            run += g_cnt[idx];
        } else if (idx == NN) {
            g_off[NN] = run;
        }
    }
}

__global__ void scatter_k(const int* __restrict__ rows, const int* __restrict__ cols,
                          const float* __restrict__ vr, const float* __restrict__ vi) {
    int e = blockIdx.x * 256 + threadIdx.x;
    if (e <= NN) g_cnt[e] = 0;            // re-zero for next graph replay
    if (e >= TOTE) return;
    int k = (e >= 2 * EDG) ? 2 : (e >= EDG) ? 1 : 0;
    int r = rows[e];
    int pos = atomicAdd(&g_cursor[r], 1);
    __half2 hv = __floats2half2_rn(vr[e], vi[e]);
    int2 pay;
    pay.x = k * NN + cols[e];
    pay.y = *(int*)&hv;
    g_epay[pos] = pay;
}

// ---------------- SpMM gather: half-warp per edge, high-MLP main loop --------
__global__ void spmm_gather_k(const float* __restrict__ bias) {
    int w    = (blockIdx.x * 256 + threadIdx.x) >> 5;
    int lane = threadIdx.x & 31;
    if (w >= NN) return;
    int half_id = lane >> 4;     // edge subgroup
    int l16     = lane & 15;     // channel group (4 channels)

    float aR0=0.f, aR1=0.f, aR2=0.f, aR3=0.f;
    float aI0=0.f, aI1=0.f, aI2=0.f, aI3=0.f;

    const char* Ab = (const char*)g_A + l16 * 16;
    int beg = g_off[w], end = g_off[w + 1];
    int e = beg;

    for (; e + 8 <= end; e += 8) {
        int b4 = e + half_id * 4;
        int2 p0 = g_epay[b4 + 0];
        int2 p1 = g_epay[b4 + 1];
        int2 p2 = g_epay[b4 + 2];
        int2 p3 = g_epay[b4 + 3];
        uint4 q0 = *(const uint4*)(Ab + (((unsigned)p0.x) << 8));
        uint4 q1 = *(const uint4*)(Ab + (((unsigned)p1.x) << 8));
        uint4 q2 = *(const uint4*)(Ab + (((unsigned)p2.x) << 8));
        uint4 q3 = *(const uint4*)(Ab + (((unsigned)p3.x) << 8));
        {
            float2 vv = __half22float2(*(const __half2*)&p0.y);
            float2 r01 = __half22float2(*(const __half2*)&q0.x);
            float2 r23 = __half22float2(*(const __half2*)&q0.y);
            float2 i01 = __half22float2(*(const __half2*)&q0.z);
            float2 i23 = __half22float2(*(const __half2*)&q0.w);
            float a = vv.x, b = vv.y;
            aR0 = fmaf(a, r01.x, fmaf(-b, i01.x, aR0));
            aI0 = fmaf(b, r01.x, fmaf( a, i01.x, aI0));
            aR1 = fmaf(a, r01.y, fmaf(-b, i01.y, aR1));
            aI1 = fmaf(b, r01.y, fmaf( a, i01.y, aI1));
            aR2 = fmaf(a, r23.x, fmaf(-b, i23.x, aR2));
            aI2 = fmaf(b, r23.x, fmaf( a, i23.x, aI2));
            aR3 = fmaf(a, r23.y, fmaf(-b, i23.y, aR3));
            aI3 = fmaf(b, r23.y, fmaf( a, i23.y, aI3));
        }
        {
            float2 vv = __half22float2(*(const __half2*)&p1.y);
            float2 r01 = __half22float2(*(const __half2*)&q1.x);
            float2 r23 = __half22float2(*(const __half2*)&q1.y);
            float2 i01 = __half22float2(*(const __half2*)&q1.z);
            float2 i23 = __half22float2(*(const __half2*)&q1.w);
            float a = vv.x, b = vv.y;
            aR0 = fmaf(a, r01.x, fmaf(-b, i01.x, aR0));
            aI0 = fmaf(b, r01.x, fmaf( a, i01.x, aI0));
            aR1 = fmaf(a, r01.y, fmaf(-b, i01.y, aR1));
            aI1 = fmaf(b, r01.y, fmaf( a, i01.y, aI1));
            aR2 = fmaf(a, r23.x, fmaf(-b, i23.x, aR2));
            aI2 = fmaf(b, r23.x, fmaf( a, i23.x, aI2));
            aR3 = fmaf(a, r23.y, fmaf(-b, i23.y, aR3));
            aI3 = fmaf(b, r23.y, fmaf( a, i23.y, aI3));
        }
        {
            float2 vv = __half22float2(*(const __half2*)&p2.y);
            float2 r01 = __half22float2(*(const __half2*)&q2.x);
            float2 r23 = __half22float2(*(const __half2*)&q2.y);
            float2 i01 = __half22float2(*(const __half2*)&q2.z);
            float2 i23 = __half22float2(*(const __half2*)&q2.w);
            float a = vv.x, b = vv.y;
            aR0 = fmaf(a, r01.x, fmaf(-b, i01.x, aR0));
            aI0 = fmaf(b, r01.x, fmaf( a, i01.x, aI0));
            aR1 = fmaf(a, r01.y, fmaf(-b, i01.y, aR1));
            aI1 = fmaf(b, r01.y, fmaf( a, i01.y, aI1));
            aR2 = fmaf(a, r23.x, fmaf(-b, i23.x, aR2));
            aI2 = fmaf(b, r23.x, fmaf( a, i23.x, aI2));
            aR3 = fmaf(a, r23.y, fmaf(-b, i23.y, aR3));
            aI3 = fmaf(b, r23.y, fmaf( a, i23.y, aI3));
        }
        {
            float2 vv = __half22float2(*(const __half2*)&p3.y);
            float2 r01 = __half22float2(*(const __half2*)&q3.x);
            float2 r23 = __half22float2(*(const __half2*)&q3.y);
            float2 i01 = __half22float2(*(const __half2*)&q3.z);
            float2 i23 = __half22float2(*(const __half2*)&q3.w);
            float a = vv.x, b = vv.y;
            aR0 = fmaf(a, r01.x, fmaf(-b, i01.x, aR0));
            aI0 = fmaf(b, r01.x, fmaf( a, i01.x, aI0));
            aR1 = fmaf(a, r01.y, fmaf(-b, i01.y, aR1));
            aI1 = fmaf(b, r01.y, fmaf( a, i01.y, aI1));
            aR2 = fmaf(a, r23.x, fmaf(-b, i23.x, aR2));
            aI2 = fmaf(b, r23.x, fmaf( a, i23.x, aI2));
            aR3 = fmaf(a, r23.y, fmaf(-b, i23.y, aR3));
            aI3 = fmaf(b, r23.y, fmaf( a, i23.y, aI3));
        }
    }
    // tail: 2 edges per iteration, guarded
    for (; e < end; e += 2) {
        int ee = e + half_id;
        int ec = min(ee, end - 1);
        int2 p = g_epay[ec];
        float2 vv = __half22float2(*(const __half2*)&p.y);
        float a = (ee < end) ? vv.x : 0.f;
        float b = (ee < end) ? vv.y : 0.f;
        uint4 q = *(const uint4*)(Ab + (((unsigned)p.x) << 8));
        float2 r01 = __half22float2(*(const __half2*)&q.x);
        float2 r23 = __half22float2(*(const __half2*)&q.y);
        float2 i01 = __half22float2(*(const __half2*)&q.z);
        float2 i23 = __half22float2(*(const __half2*)&q.w);
        aR0 = fmaf(a, r01.x, fmaf(-b, i01.x, aR0));
        aI0 = fmaf(b, r01.x, fmaf( a, i01.x, aI0));
        aR1 = fmaf(a, r01.y, fmaf(-b, i01.y, aR1));
        aI1 = fmaf(b, r01.y, fmaf( a, i01.y, aI1));
        aR2 = fmaf(a, r23.x, fmaf(-b, i23.x, aR2));
        aI2 = fmaf(b, r23.x, fmaf( a, i23.x, aI2));
        aR3 = fmaf(a, r23.y, fmaf(-b, i23.y, aR3));
        aI3 = fmaf(b, r23.y, fmaf( a, i23.y, aI3));
    }

    // combine the two half-warps' partials
    aR0 += __shfl_xor_sync(0xffffffffu, aR0, 16);
    aR1 += __shfl_xor_sync(0xffffffffu, aR1, 16);
    aR2 += __shfl_xor_sync(0xffffffffu, aR2, 16);
    aR3 += __shfl_xor_sync(0xffffffffu, aR3, 16);
    aI0 += __shfl_xor_sync(0xffffffffu, aI0, 16);
    aI1 += __shfl_xor_sync(0xffffffffu, aI1, 16);
    aI2 += __shfl_xor_sync(0xffffffffu, aI2, 16);
    aI3 += __shfl_xor_sync(0xffffffffu, aI3, 16);

    if (half_id == 0) {
        float4 bv = *(const float4*)&bias[l16 * 4];
        float r0 = aR0 + bv.x, r1 = aR1 + bv.y, r2 = aR2 + bv.z, r3 = aR3 + bv.w;
        float i0 = aI0 + bv.x, i1 = aI1 + bv.y, i2 = aI2 + bv.z, i3 = aI3 + bv.w;
        float4 hr, hi;
        hr.x = (r0 >= 0.f) ? r0 : 0.f;  hi.x = (r0 >= 0.f) ? i0 : 0.f;
        hr.y = (r1 >= 0.f) ? r1 : 0.f;  hi.y = (r1 >= 0.f) ? i1 : 0.f;
        hr.z = (r2 >= 0.f) ? r2 : 0.f;  hi.z = (r2 >= 0.f) ? i2 : 0.f;
        hr.w = (r3 >= 0.f) ? r3 : 0.f;  hi.w = (r3 >= 0.f) ? i3 : 0.f;
        *(float4*)&g_Hr[w * NF + l16 * 4] = hr;
        *(float4*)&g_Hi[w * NF + l16 * 4] = hi;
    }
}

// ---------------- CBAM channel attention -------------------------------------
__global__ void zero_cmean_k() {
    if (threadIdx.x < CCH) g_cmean[threadIdx.x] = 0.f;
}

__global__ void chan_sum_k() {
    const int NPB = 512;
    int t = threadIdx.x;            // 256
    int c = t & 127;
    int half = t >> 7;
    int n0 = blockIdx.x * NPB;
    int n1 = min(n0 + NPB, NN);
    const float* src = (c < NF) ? g_Hr : g_Hi;
    int cc = c & (NF - 1);
    float s = 0.f;
    for (int n = n0 + half; n < n1; n += 2) s += src[n * NF + cc];
    __shared__ float sm[256];
    sm[t] = s;
    __syncthreads();
    if (t < 128) atomicAdd(&g_cmean[c], sm[t] + sm[t + 128]);
}

__global__ void ca_k(const float* __restrict__ w1, const float* __restrict__ w2) {
    __shared__ float avg[CCH];
    __shared__ float hid[8];
    int t = threadIdx.x;            // 128
    avg[t] = g_cmean[t] * (1.f / (float)NN);
    __syncthreads();
    if (t < 8) {
        float s = 0.f;
        #pragma unroll 4
        for (int c = 0; c < CCH; c++) s += w1[t * CCH + c] * avg[c];
        hid[t] = fmaxf(s, 0.f);
    }
    __syncthreads();
    float o = 0.f;
    #pragma unroll
    for (int r = 0; r < 8; r++) o += w2[t * 8 + r] * hid[r];
    g_ca[t] = 1.f / (1.f + expf(-o));
}

// ---------------- spatial stats (after CA scaling) ---------------------------
__global__ void sstat_k() {
    __shared__ float ca[CCH];
    if (threadIdx.x < CCH) ca[threadIdx.x] = g_ca[threadIdx.x];
    __syncthreads();
    int n = blockIdx.x * blockDim.x + threadIdx.x;
    if (n >= NN) return;
    float sum = 0.f, mx = -1e30f;
    const float4* hr = (const float4*)&g_Hr[n * NF];
    #pragma unroll
    for (int j = 0; j < 16; j++) {
        float4 v = hr[j];
        float a0 = v.x * ca[j*4+0], a1 = v.y * ca[j*4+1];
        float a2 = v.z * ca[j*4+2], a3 = v.w * ca[j*4+3];
        sum += a0 + a1 + a2 + a3;
        mx = fmaxf(mx, fmaxf(fmaxf(a0, a1), fmaxf(a2, a3)));
    }
    const float4* hi = (const float4*)&g_Hi[n * NF];
    #pragma unroll
    for (int j = 0; j < 16; j++) {
        float4 v = hi[j];
        float a0 = v.x * ca[64+j*4+0], a1 = v.y * ca[64+j*4+1];
        float a2 = v.z * ca[64+j*4+2], a3 = v.w * ca[64+j*4+3];
        sum += a0 + a1 + a2 + a3;
        mx = fmaxf(mx, fmaxf(fmaxf(a0, a1), fmaxf(a2, a3)));
    }
    g_smean[n] = sum * (1.f / (float)CCH);
    g_smax[n]  = mx;
}

// ---------------- spatial attention + final conv + log_softmax ---------------
__global__ void final_k(const float* __restrict__ sa_w,
                        const float* __restrict__ conv_w,
                        const float* __restrict__ conv_b,
                        float* __restrict__ out) {
    __shared__ float ca[CCH];
    __shared__ float cw[LABEL * CCH];
    __shared__ float cb[LABEL];
    __shared__ float sw[14];
    int t = threadIdx.x;
    if (t < CCH) ca[t] = g_ca[t];
    for (int idx = t; idx < LABEL * CCH; idx += blockDim.x) cw[idx] = conv_w[idx];
    if (t < LABEL) cb[t] = conv_b[t];
    if (t < 14) sw[t] = sa_w[t];
    __syncthreads();

    int n = blockIdx.x * blockDim.x + t;
    if (n >= NN) return;

    float s = 0.f;
    #pragma unroll
    for (int tap = 0; tap < 7; tap++) {
        int m = n - 3 + tap;
        if (m >= 0 && m < NN) s += sw[tap] * g_smean[m] + sw[7 + tap] * g_smax[m];
    }
    float sa = 1.f / (1.f + expf(-s));

    float acc[LABEL];
    #pragma unroll
    for (int l = 0; l < LABEL; l++) acc[l] = cb[l];

    const float* hr = &g_Hr[n * NF];
    const float* hi = &g_Hi[n * NF];
    #pragma unroll 4
    for (int c = 0; c < NF; c++) {
        float xv = hr[c] * ca[c] * sa;
        #pragma unroll
        for (int l = 0; l < LABEL; l++) acc[l] += cw[l * CCH + c] * xv;
    }
    #pragma unroll 4
    for (int c = 0; c < NF; c++) {
        float xv = hi[c] * ca[NF + c] * sa;
        #pragma unroll
        for (int l = 0; l < LABEL; l++) acc[l] += cw[l * CCH + NF + c] * xv;
    }

    float mx = acc[0];
    #pragma unroll
    for (int l = 1; l < LABEL; l++) mx = fmaxf(mx, acc[l]);
    float se = 0.f;
    #pragma unroll
    for (int l = 0; l < LABEL; l++) se += expf(acc[l] - mx);
    float lse = logf(se) + mx;
    #pragma unroll
    for (int l = 0; l < LABEL; l++) out[l * NN + n] = acc[l] - lse;
}

// ---------------- launch sequence --------------------------------------------
extern "C" void kernel_launch(void* const* d_in, const int* in_sizes, int n_in,
                              void* d_out, int out_size) {
    const float* Xr    = (const float*)d_in[0];
    const float* Xi    = (const float*)d_in[1];
    const int*   rows  = (const int*)  d_in[2];
    const int*   cols  = (const int*)  d_in[3];
    const float* vr    = (const float*)d_in[4];
    const float* vi    = (const float*)d_in[5];
    const float* w0    = (const float*)d_in[6];
    const float* b0    = (const float*)d_in[7];
    const float* w1    = (const float*)d_in[8];
    const float* b1    = (const float*)d_in[9];
    const float* w2    = (const float*)d_in[10];
    const float* b2    = (const float*)d_in[11];
    const float* caw1  = (const float*)d_in[12];
    const float* caw2  = (const float*)d_in[13];
    const float* saw   = (const float*)d_in[14];
    const float* convw = (const float*)d_in[15];
    const float* convb = (const float*)d_in[16];
    float* out = (float*)d_out;

    const dim3 gemm_grid((NN + 63) / 64, 6);
    const int edge_blocks   = (TOTE + 255) / 256;
    const int gather_blocks = (NN * 32 + 255) / 256;
    const int node_blocks   = (NN + 255) / 256;

    // ---- CSR build (reused by all 3 layers) ----
    hist_k<<<edge_blocks, 256>>>(rows);                       // launch 0
    scan_k<<<1, 1024>>>();                                    // launch 1
    scatter_k<<<edge_blocks, 256>>>(rows, cols, vr, vi);      // launch 2

    // ---- layer 0 (FIN=128, inputs from d_in) ----
    gemm_t<INC, false><<<gemm_grid, 128>>>(Xr, Xi, w0);       // launch 3 (profiled)
    spmm_gather_k<<<gather_blocks, 256>>>(b0);

    // ---- layer 1 ----
    gemm_t<NF, true><<<gemm_grid, 128>>>(nullptr, nullptr, w1);
    spmm_gather_k<<<gather_blocks, 256>>>(b1);

    // ---- layer 2 ----
    gemm_t<NF, true><<<gemm_grid, 128>>>(nullptr, nullptr, w2);
    spmm_gather_k<<<gather_blocks, 256>>>(b2);

    // ---- CBAM + head ----
    zero_cmean_k<<<1, 128>>>();
    chan_sum_k<<<(NN + 511) / 512, 256>>>();
    ca_k<<<1, 128>>>(caw1, caw2);
    sstat_k<<<node_blocks, 256>>>();
    final_k<<<node_blocks, 256>>>(saw, convw, convb, out);
}